// round 7
// baseline (speedup 1.0000x reference)
#include <cuda_runtime.h>
#include <cstdint>
#include <cstddef>

// Problem constants
#define T_SEQ  2048
#define NHEAD  16
#define HDIM   1024
#define HD     64
#define BATCH  2
#define MROWS  (BATCH * T_SEQ)   // 4096

// Scratch (device globals; no allocations allowed)
__device__ float g_qkv[MROWS * 3 * HDIM];
__device__ float g_Q[BATCH * NHEAD * T_SEQ * HD];    // [bh][t][d], tf32, pre-scaled
__device__ float g_K[BATCH * NHEAD * T_SEQ * HD];    // [bh][t][d], tf32
__device__ float g_V[BATCH * NHEAD * T_SEQ * HD];    // [bh][d][t]  (TRANSPOSED), tf32
__device__ float g_attn[MROWS * HDIM];
__device__ float g_Ar[MROWS * HDIM];                 // tf32-rounded hidden
__device__ float g_Bt1[3 * HDIM * HDIM];             // w_qkv^T rounded [3072,1024]
__device__ float g_Bt2[HDIM * HDIM];                 // w_out^T rounded [1024,1024]

// ---------------------------------------------------------------------------
// Helpers
// ---------------------------------------------------------------------------
__device__ __forceinline__ float to_tf32(float x) {
    uint32_t u;
    asm("cvt.rna.tf32.f32 %0, %1;" : "=r"(u) : "f"(x));
    return __uint_as_float(u);
}

__device__ __forceinline__ void cp16(uint32_t dst, const void* src) {
    asm volatile("cp.async.cg.shared.global [%0], [%1], 16;\n" :: "r"(dst), "l"(src));
}
__device__ __forceinline__ void cp_commit() {
    asm volatile("cp.async.commit_group;\n");
}
__device__ __forceinline__ void cp_wait1() {
    asm volatile("cp.async.wait_group 1;\n");
}
__device__ __forceinline__ void cp_wait0() {
    asm volatile("cp.async.wait_group 0;\n");
}

__device__ __forceinline__ void mma_tf32(float* c, const uint32_t* a, const uint32_t* b) {
    asm volatile(
        "mma.sync.aligned.m16n8k8.row.col.f32.tf32.tf32.f32 "
        "{%0,%1,%2,%3}, {%4,%5,%6,%7}, {%8,%9}, {%0,%1,%2,%3};"
        : "+f"(c[0]), "+f"(c[1]), "+f"(c[2]), "+f"(c[3])
        : "r"(a[0]), "r"(a[1]), "r"(a[2]), "r"(a[3]), "r"(b[0]), "r"(b[1]));
}

__device__ __forceinline__ void ldsm4(uint32_t* r, uint32_t addr) {
    asm volatile("ldmatrix.sync.aligned.m8n8.x4.shared.b16 {%0,%1,%2,%3}, [%4];"
        : "=r"(r[0]), "=r"(r[1]), "=r"(r[2]), "=r"(r[3]) : "r"(addr));
}

// ---------------------------------------------------------------------------
// tf32 mma.sync GEMM, 3-stage single-sync pipeline.
// C[M,N] = A[M,K] @ Bt[N,K]^T (+bias); 128x128x16 CTA tile, 256 threads,
// 8 warps (2x4), warp tile 64x32, ldmatrix fragments.
// ---------------------------------------------------------------------------
#define ASTR 20                          // floats per smem row (16 + 4 pad)
#define STAGE_FLOATS (2 * 128 * ASTR)    // A tile then B tile
#define STAGE_BYTES (STAGE_FLOATS * 4)   // 20480
#define NSTAGE 3
#define GEMM_SMEM (NSTAGE * STAGE_BYTES) // 61440

__global__ __launch_bounds__(256) void tf32_mma_gemm(
    const float* __restrict__ A, const float* __restrict__ Bt,
    const float* __restrict__ bias, float* __restrict__ C,
    int N, int K)
{
    extern __shared__ __align__(128) float smf[];
    const uint32_t sbase = (uint32_t)__cvta_generic_to_shared(smf);

    const int tid = threadIdx.x, lane = tid & 31, w = tid >> 5;
    const int wm = w & 1, wn = w >> 1;           // warp 2x4 grid
    const int g = lane >> 2, tig = lane & 3;
    const int bm = blockIdx.y * 128, bn = blockIdx.x * 128;

    // cp.async mapping
    const int lm0 = tid >> 2;            // 0..63
    const int lkq = (tid & 3) * 4;       // 0,4,8,12
    const float* Ag0 = A + (size_t)(bm + lm0) * K + lkq;
    const float* Ag1 = Ag0 + (size_t)64 * K;
    const float* Bg0 = Bt + (size_t)(bn + lm0) * K + lkq;
    const float* Bg1 = Bg0 + (size_t)64 * K;
    const uint32_t offA0 = (lm0 * ASTR + lkq) * 4;
    const uint32_t offA1 = ((lm0 + 64) * ASTR + lkq) * 4;
    const uint32_t offB0 = 128 * ASTR * 4 + offA0;
    const uint32_t offB1 = 128 * ASTR * 4 + offA1;

    // ldmatrix per-lane offsets
    const uint32_t a_lrow = (lane & 7) + ((lane >> 3) & 1) * 8;
    const uint32_t a_lk = (lane >> 4) * 4;
    const uint32_t b_lrow = (lane & 7) + ((lane >> 4) & 1) * 8;
    const uint32_t b_lk = ((lane >> 3) & 1) * 4;

    const uint32_t aAddr0 = sbase + ((wm * 64 + a_lrow) * ASTR + a_lk) * 4;
    const uint32_t bAddr0 = sbase + (128 * ASTR + (wn * 32 + b_lrow) * ASTR + b_lk) * 4;

    const int nchunks = K / 16;

    // Prologue: chunks 0,1 into stages 0,1
#pragma unroll
    for (int s = 0; s < 2; s++) {
        uint32_t so = sbase + s * STAGE_BYTES;
        cp16(so + offA0, Ag0 + s * 16);
        cp16(so + offA1, Ag1 + s * 16);
        cp16(so + offB0, Bg0 + s * 16);
        cp16(so + offB1, Bg1 + s * 16);
        cp_commit();
    }

    float acc[4][4][4] = {};
    int cur = 0, nxt = 2;

    for (int c = 0; c < nchunks; c++) {
        cp_wait1();        // chunk c landed (this thread)
        __syncthreads();   // chunk c visible; all warps done reading stage (c-1)%3

        // Issue chunk c+2 into the just-freed stage
        if (c + 2 < nchunks) {
            uint32_t so = sbase + nxt * STAGE_BYTES;
            const int k0 = (c + 2) * 16;
            cp16(so + offA0, Ag0 + k0);
            cp16(so + offA1, Ag1 + k0);
            cp16(so + offB0, Bg0 + k0);
            cp16(so + offB1, Bg1 + k0);
        }
        cp_commit();
        nxt = (nxt + 1 == NSTAGE) ? 0 : nxt + 1;

        const uint32_t st = cur * STAGE_BYTES;
        cur = (cur + 1 == NSTAGE) ? 0 : cur + 1;

#pragma unroll
        for (int ks = 0; ks < 16; ks += 8) {
            uint32_t afr[4][4];
#pragma unroll
            for (int i = 0; i < 4; i++)
                ldsm4(afr[i], aAddr0 + st + (i * 16 * ASTR + ks) * 4);
            uint32_t bfr[2][4];
#pragma unroll
            for (int jp = 0; jp < 2; jp++)
                ldsm4(bfr[jp], bAddr0 + st + (jp * 16 * ASTR + ks) * 4);
#pragma unroll
            for (int i = 0; i < 4; i++)
#pragma unroll
                for (int jp = 0; jp < 2; jp++) {
                    mma_tf32(acc[i][jp * 2],     afr[i], bfr[jp]);
                    mma_tf32(acc[i][jp * 2 + 1], afr[i], bfr[jp] + 2);
                }
        }
    }

#pragma unroll
    for (int i = 0; i < 4; i++) {
        const int r0 = bm + wm * 64 + i * 16 + g;
#pragma unroll
        for (int j = 0; j < 4; j++) {
            const int c0 = bn + wn * 32 + j * 8 + tig * 2;
            float bx = 0.f, by = 0.f;
            if (bias) { bx = bias[c0]; by = bias[c0 + 1]; }
            float2 o0 = make_float2(acc[i][j][0] + bx, acc[i][j][1] + by);
            float2 o1 = make_float2(acc[i][j][2] + bx, acc[i][j][3] + by);
            *(float2*)&C[(size_t)r0 * N + c0] = o0;
            *(float2*)&C[(size_t)(r0 + 8) * N + c0] = o1;
        }
    }
}

// ---------------------------------------------------------------------------
// Prep: tf32-round copy, and transpose+round (src[K,N] -> dst[N,K])
// ---------------------------------------------------------------------------
__global__ __launch_bounds__(256) void round_tf32_kernel(
    const float* __restrict__ src, float* __restrict__ dst)
{
    int i = blockIdx.x * 256 + threadIdx.x;
    float4 v = ((const float4*)src)[i];
    v.x = to_tf32(v.x); v.y = to_tf32(v.y);
    v.z = to_tf32(v.z); v.w = to_tf32(v.w);
    ((float4*)dst)[i] = v;
}

__global__ __launch_bounds__(256) void transpose_round_kernel(
    const float* __restrict__ src, float* __restrict__ dst, int K, int N)
{
    __shared__ float t[32][33];
    int n0 = blockIdx.x * 32, k0 = blockIdx.y * 32;
    int x = threadIdx.x & 31, y = threadIdx.x >> 5;   // 32 x 8
#pragma unroll
    for (int i = 0; i < 4; i++)
        t[y + i * 8][x] = src[(size_t)(k0 + y + i * 8) * N + n0 + x];
    __syncthreads();
#pragma unroll
    for (int i = 0; i < 4; i++)
        dst[(size_t)(n0 + y + i * 8) * K + k0 + x] = to_tf32(t[x][y + i * 8]);
}

// ---------------------------------------------------------------------------
// RoPE (Q/K only, coalesced) + separate tiled V transpose.
// ---------------------------------------------------------------------------
__global__ __launch_bounds__(256) void rope_kernel(
    const float* __restrict__ qkv,
    float* __restrict__ Q, float* __restrict__ K)
{
    const int bt = blockIdx.x;
    const int b = bt >> 11;
    const int t = bt & 2047;
    const float* row = qkv + (size_t)bt * (3 * HDIM);
    const float LN1E4_OVER_32 = 0.28782313662425575f;  // ln(10000)/32

#pragma unroll
    for (int it = 0; it < 4; it++) {
        int idx = it * 256 + threadIdx.x;
        int h = idx >> 6;
        int d = idx & 63;
        const float* base = row + h * (3 * HD);
        float qv = base[d];
        float kv = base[HD + d];
        int fi = d & 31;
        float inv = expf(-(float)fi * LN1E4_OVER_32);
        float ang = (float)t * inv;
        float sv, cv;
        sincosf(ang, &sv, &cv);
        float qrot = (d < 32) ? -base[d + 32] : base[d - 32];
        float krot = (d < 32) ? -base[HD + d + 32] : base[HD + d - 32];
        int bh = b * NHEAD + h;
        size_t o = ((size_t)bh * T_SEQ + t) * HD + d;
        Q[o] = to_tf32((qv * cv + qrot * sv) * 0.125f);
        K[o] = to_tf32(kv * cv + krot * sv);
    }
}

// V slice of qkv -> Vt [bh][d][t], tf32-rounded, tiled transpose.
__global__ __launch_bounds__(256) void vtrans_kernel(
    const float* __restrict__ qkv, float* __restrict__ Vt)
{
    __shared__ float t[32][33];
    const int t0 = blockIdx.x * 32;
    const int d0 = blockIdx.y * 32;
    const int bh = blockIdx.z;
    const int b = bh >> 4, h = bh & 15;
    const int x = threadIdx.x & 31, y = threadIdx.x >> 5;

#pragma unroll
    for (int i = 0; i < 4; i++)
        t[y + i * 8][x] =
            qkv[(size_t)(b * T_SEQ + t0 + y + i * 8) * (3 * HDIM) + h * 192 + 128 + d0 + x];
    __syncthreads();
#pragma unroll
    for (int i = 0; i < 4; i++)
        Vt[((size_t)bh * HD + d0 + y + i * 8) * T_SEQ + t0 + x] = to_tf32(t[x][y + i * 8]);
}

// ---------------------------------------------------------------------------
// Flash attention with tf32 mma.sync + ldmatrix, pipelined K/V loads:
//   wait K(j) | sync | issue V(j) | S-MMA | sync | issue K(j+1) |
//   softmax | wait V(j) | sync | PV
// ---------------------------------------------------------------------------
#define AQS 68   // smem row stride (floats): conflict-free for ldmatrix
#define ATT_SMEM ((128 * AQS + 64 * AQS + 64 * AQS + 128 * AQS) * 4 + 64 * 4)

__global__ __launch_bounds__(256, 2) void attn_mma_kernel(
    const float* __restrict__ Q, const float* __restrict__ K,
    const float* __restrict__ Vt, const int* __restrict__ amask,
    float* __restrict__ out)
{
    extern __shared__ __align__(128) float s[];
    float* Qs  = s;                    // [128][AQS]
    float* Ks  = Qs + 128 * AQS;       // [64][AQS]   Ks[key][d]
    float* Vts = Ks + 64 * AQS;        // [64][AQS]   Vts[d][key]
    float* Ps  = Vts + 64 * AQS;       // [128][AQS]
    int* smask = (int*)(Ps + 128 * AQS);

    const uint32_t sb  = (uint32_t)__cvta_generic_to_shared(s);
    const uint32_t ksb = (uint32_t)__cvta_generic_to_shared(Ks);
    const uint32_t vsb = (uint32_t)__cvta_generic_to_shared(Vts);
    const uint32_t psb = (uint32_t)__cvta_generic_to_shared(Ps);

    const int tid = threadIdx.x, lane = tid & 31, w = tid >> 5;
    const int g = lane >> 2, tig = lane & 3;
    const int qb = blockIdx.x;
    const int bh = blockIdx.y;
    const int b = bh >> 4, h = bh & 15;

    // ldmatrix per-lane offsets
    const uint32_t a_lrow = (lane & 7) + ((lane >> 3) & 1) * 8;
    const uint32_t a_lk = (lane >> 4) * 4;
    const uint32_t b_lrow = (lane & 7) + ((lane >> 4) & 1) * 8;
    const uint32_t b_lk = ((lane >> 3) & 1) * 4;

    const uint32_t qAddr0 = sb  + ((w * 16 + a_lrow) * AQS + a_lk) * 4;
    const uint32_t pAddr0 = psb + ((w * 16 + a_lrow) * AQS + a_lk) * 4;
    const uint32_t kAddr0 = ksb + (b_lrow * AQS + b_lk) * 4;
    const uint32_t vAddr0 = vsb + (b_lrow * AQS + b_lk) * 4;

    // Prologue: Q tile (group 0) + K(0) (group 1)
    const float* Qg = Q + ((size_t)bh * T_SEQ + qb * 128) * HD;
#pragma unroll
    for (int it = 0; it < 8; it++) {
        int idx = it * 256 + tid;
        int r = idx >> 4, c4 = (idx & 15) << 2;
        cp16(sb + (r * AQS + c4) * 4, Qg + r * HD + c4);
    }
    cp_commit();

    const float* Kbase = K + (size_t)bh * T_SEQ * HD;
    const float* Vbase = Vt + (size_t)bh * HD * T_SEQ;

    {
        const float* Kg = Kbase;   // jb = 0
#pragma unroll
        for (int it = 0; it < 4; it++) {
            int idx = it * 256 + tid;
            int r = idx >> 4, c4 = (idx & 15) << 2;
            cp16(ksb + (r * AQS + c4) * 4, Kg + r * HD + c4);
        }
    }
    cp_commit();

    float accO[8][4] = {};
    float m0 = -1e30f, m1 = -1e30f, l0 = 0.f, l1 = 0.f;

    const int qrow0 = qb * 128 + w * 16 + g;
    const int qrow1 = qrow0 + 8;
    const int nkb = 2 * qb + 2;

    for (int jb = 0; jb < nkb; jb++) {
        // 1) K(jb) (and everything older) landed
        cp_wait0();
        __syncthreads();   // K visible; all warps past PV(jb-1) -> Vts free

        // 2) issue V(jb) loads + mask
        {
            const float* Vg = Vbase + jb * 64;
#pragma unroll
            for (int it = 0; it < 4; it++) {
                int idx = it * 256 + tid;
                int r = idx >> 4, c4 = (idx & 15) << 2;
                cp16(vsb + (r * AQS + c4) * 4, Vg + (size_t)r * T_SEQ + c4);
            }
        }
        if (tid < 64) smask[tid] = amask[b * T_SEQ + jb * 64 + tid];
        cp_commit();       // group: V(jb)

        // 3) S = Q_tile @ K_tile^T
        float sacc[8][4];
#pragma unroll
        for (int j = 0; j < 8; j++)
            sacc[j][0] = sacc[j][1] = sacc[j][2] = sacc[j][3] = 0.f;
#pragma unroll
        for (int ks = 0; ks < 8; ks++) {
            uint32_t af[4];
            ldsm4(af, qAddr0 + ks * 32);
#pragma unroll
            for (int jp = 0; jp < 4; jp++) {
                uint32_t bf[4];
                ldsm4(bf, kAddr0 + (jp * 16 * AQS + ks * 8) * 4);
                mma_tf32(sacc[jp * 2],     af, bf);
                mma_tf32(sacc[jp * 2 + 1], af, bf + 2);
            }
        }

        __syncthreads();   // all warps done reading Ks; smask visible

        // 4) issue K(jb+1) loads (hidden behind softmax + PV)
        if (jb + 1 < nkb) {
            const float* Kg = Kbase + (size_t)(jb + 1) * 64 * HD;
#pragma unroll
            for (int it = 0; it < 4; it++) {
                int idx = it * 256 + tid;
                int r = idx >> 4, c4 = (idx & 15) << 2;
                cp16(ksb + (r * AQS + c4) * 4, Kg + r * HD + c4);
            }
        }
        cp_commit();       // group: K(jb+1) (possibly empty)

        // 5) mask + online softmax (registers)
        float mx0 = m0, mx1 = m1;
#pragma unroll
        for (int j = 0; j < 8; j++) {
            int c = j * 8 + 2 * tig;
            int colg = jb * 64 + c;
            bool v0 = smask[c]     && (colg     <= qrow0);
            bool v1 = smask[c + 1] && (colg + 1 <= qrow0);
            bool v2 = smask[c]     && (colg     <= qrow1);
            bool v3 = smask[c + 1] && (colg + 1 <= qrow1);
            sacc[j][0] = v0 ? sacc[j][0] : -1e30f;
            sacc[j][1] = v1 ? sacc[j][1] : -1e30f;
            sacc[j][2] = v2 ? sacc[j][2] : -1e30f;
            sacc[j][3] = v3 ? sacc[j][3] : -1e30f;
            mx0 = fmaxf(mx0, fmaxf(sacc[j][0], sacc[j][1]));
            mx1 = fmaxf(mx1, fmaxf(sacc[j][2], sacc[j][3]));
        }
        mx0 = fmaxf(mx0, __shfl_xor_sync(0xffffffff, mx0, 1));
        mx0 = fmaxf(mx0, __shfl_xor_sync(0xffffffff, mx0, 2));
        mx1 = fmaxf(mx1, __shfl_xor_sync(0xffffffff, mx1, 1));
        mx1 = fmaxf(mx1, __shfl_xor_sync(0xffffffff, mx1, 2));
        float corr0 = __expf(m0 - mx0);
        float corr1 = __expf(m1 - mx1);
        m0 = mx0; m1 = mx1;

        float sum0 = 0.f, sum1 = 0.f;
        float* prow0 = Ps + (w * 16 + g) * AQS;
        float* prow1 = prow0 + 8 * AQS;
#pragma unroll
        for (int j = 0; j < 8; j++) {
            int c = j * 8 + 2 * tig;
            float p0 = to_tf32(__expf(sacc[j][0] - mx0));
            float p1 = to_tf32(__expf(sacc[j][1] - mx0));
            float p2 = to_tf32(__expf(sacc[j][2] - mx1));
            float p3 = to_tf32(__expf(sacc[j][3] - mx1));
            sum0 += p0 + p1;
            sum1 += p2 + p3;
            *(float2*)&prow0[c] = make_float2(p0, p1);
            *(float2*)&prow1[c] = make_float2(p2, p3);
        }
        sum0 += __shfl_xor_sync(0xffffffff, sum0, 1);
        sum0 += __shfl_xor_sync(0xffffffff, sum0, 2);
        sum1 += __shfl_xor_sync(0xffffffff, sum1, 1);
        sum1 += __shfl_xor_sync(0xffffffff, sum1, 2);
        l0 = l0 * corr0 + sum0;
        l1 = l1 * corr1 + sum1;

#pragma unroll
        for (int j = 0; j < 8; j++) {
            accO[j][0] *= corr0; accO[j][1] *= corr0;
            accO[j][2] *= corr1; accO[j][3] *= corr1;
        }
        __syncwarp();

        // 6) wait V(jb) (K(jb+1) may stay in flight), then PV
        cp_wait1();
        __syncthreads();   // V visible to all warps

#pragma unroll
        for (int ks = 0; ks < 8; ks++) {
            uint32_t pa[4];
            ldsm4(pa, pAddr0 + ks * 32);
#pragma unroll
            for (int jp = 0; jp < 4; jp++) {
                uint32_t bf[4];
                ldsm4(bf, vAddr0 + (jp * 16 * AQS + ks * 8) * 4);
                mma_tf32(accO[jp * 2],     pa, bf);
                mma_tf32(accO[jp * 2 + 1], pa, bf + 2);
            }
        }
    }

    // ---- epilogue ----
    float inv0 = 1.f / l0, inv1 = 1.f / l1;
    const int r0 = b * T_SEQ + qb * 128 + w * 16 + g;
#pragma unroll
    for (int j = 0; j < 8; j++) {
        int c = h * HD + j * 8 + 2 * tig;
        float2 o0 = make_float2(to_tf32(accO[j][0] * inv0), to_tf32(accO[j][1] * inv0));
        float2 o1 = make_float2(to_tf32(accO[j][2] * inv1), to_tf32(accO[j][3] * inv1));
        *(float2*)&out[(size_t)r0 * HDIM + c] = o0;
        *(float2*)&out[(size_t)(r0 + 8) * HDIM + c] = o1;
    }
}

// ---------------------------------------------------------------------------
// Launch
// ---------------------------------------------------------------------------
extern "C" void kernel_launch(void* const* d_in, const int* in_sizes, int n_in,
                              void* d_out, int out_size)
{
    const float* hidden = (const float*)d_in[0];
    const int*   amask  = (const int*)d_in[1];
    const float* w_qkv  = (const float*)d_in[2];
    const float* b_qkv  = (const float*)d_in[3];
    const float* w_out  = (const float*)d_in[4];
    float* out = (float*)d_out;

    float *qkv, *Q, *K, *V, *attn, *Ar, *Bt1, *Bt2;
    cudaGetSymbolAddress((void**)&qkv,  g_qkv);
    cudaGetSymbolAddress((void**)&Q,    g_Q);
    cudaGetSymbolAddress((void**)&K,    g_K);
    cudaGetSymbolAddress((void**)&V,    g_V);
    cudaGetSymbolAddress((void**)&attn, g_attn);
    cudaGetSymbolAddress((void**)&Ar,   g_Ar);
    cudaGetSymbolAddress((void**)&Bt1,  g_Bt1);
    cudaGetSymbolAddress((void**)&Bt2,  g_Bt2);

    cudaFuncSetAttribute(attn_mma_kernel, cudaFuncAttributeMaxDynamicSharedMemorySize,
                         ATT_SMEM);
    cudaFuncSetAttribute(tf32_mma_gemm, cudaFuncAttributeMaxDynamicSharedMemorySize,
                         GEMM_SMEM);

    // 0) tf32-round A; transpose+round weights
    round_tf32_kernel<<<MROWS * HDIM / 4 / 256, 256>>>(hidden, Ar);
    transpose_round_kernel<<<dim3(3 * HDIM / 32, HDIM / 32), 256>>>(w_qkv, Bt1, HDIM, 3 * HDIM);
    transpose_round_kernel<<<dim3(HDIM / 32, HDIM / 32), 256>>>(w_out, Bt2, HDIM, HDIM);

    // 1) qkv = Ar @ w_qkv + b_qkv (tf32 mma.sync, 3-stage pipeline)
    tf32_mma_gemm<<<dim3(3 * HDIM / 128, MROWS / 128), 256, GEMM_SMEM>>>(
        Ar, Bt1, b_qkv, qkv, 3 * HDIM, HDIM);

    // 2) RoPE (Q/K) + V transpose
    rope_kernel<<<MROWS, 256>>>(qkv, Q, K);
    vtrans_kernel<<<dim3(T_SEQ / 32, HD / 32, BATCH * NHEAD), 256>>>(qkv, V);

    // 3) tf32 mma flash attention -> attn [B,T,H] (tf32-rounded)
    attn_mma_kernel<<<dim3(T_SEQ / 128, BATCH * NHEAD), 256, ATT_SMEM>>>(
        Q, K, V, amask, attn);

    // 4) out = attn @ w_out (tf32 mma.sync, 3-stage pipeline)
    tf32_mma_gemm<<<dim3(HDIM / 128, MROWS / 128), 256, GEMM_SMEM>>>(
        attn, Bt2, nullptr, out, HDIM, HDIM);
}

// round 8
// speedup vs baseline: 1.0275x; 1.0275x over previous
#include <cuda_runtime.h>
#include <cstdint>
#include <cstddef>

// Problem constants
#define T_SEQ  2048
#define NHEAD  16
#define HDIM   1024
#define HD     64
#define BATCH  2
#define MROWS  (BATCH * T_SEQ)   // 4096

// Scratch (device globals; no allocations allowed)
__device__ float g_qkv[MROWS * 3 * HDIM];
__device__ float g_Q[BATCH * NHEAD * T_SEQ * HD];    // [bh][t][d], tf32, pre-scaled
__device__ float g_K[BATCH * NHEAD * T_SEQ * HD];    // [bh][t][d], tf32
__device__ float g_V[BATCH * NHEAD * T_SEQ * HD];    // [bh][d][t]  (TRANSPOSED), tf32
__device__ float g_attn[MROWS * HDIM];
__device__ float g_Bt1[3 * HDIM * HDIM];             // w_qkv^T rounded [3072,1024]
__device__ float g_Bt2[HDIM * HDIM];                 // w_out^T rounded [1024,1024]

// ---------------------------------------------------------------------------
// Helpers
// ---------------------------------------------------------------------------
__device__ __forceinline__ float to_tf32(float x) {
    uint32_t u;
    asm("cvt.rna.tf32.f32 %0, %1;" : "=r"(u) : "f"(x));
    return __uint_as_float(u);
}

__device__ __forceinline__ uint32_t rnd_u32(uint32_t x) {
    uint32_t u;
    asm("cvt.rna.tf32.f32 %0, %1;" : "=r"(u) : "r"(x));
    return u;
}

__device__ __forceinline__ void cp16(uint32_t dst, const void* src) {
    asm volatile("cp.async.cg.shared.global [%0], [%1], 16;\n" :: "r"(dst), "l"(src));
}
__device__ __forceinline__ void cp_commit() {
    asm volatile("cp.async.commit_group;\n");
}
__device__ __forceinline__ void cp_wait2() {
    asm volatile("cp.async.wait_group 2;\n");
}
__device__ __forceinline__ void cp_wait1() {
    asm volatile("cp.async.wait_group 1;\n");
}
__device__ __forceinline__ void cp_wait0() {
    asm volatile("cp.async.wait_group 0;\n");
}

__device__ __forceinline__ void mma_tf32(float* c, const uint32_t* a, const uint32_t* b) {
    asm volatile(
        "mma.sync.aligned.m16n8k8.row.col.f32.tf32.tf32.f32 "
        "{%0,%1,%2,%3}, {%4,%5,%6,%7}, {%8,%9}, {%0,%1,%2,%3};"
        : "+f"(c[0]), "+f"(c[1]), "+f"(c[2]), "+f"(c[3])
        : "r"(a[0]), "r"(a[1]), "r"(a[2]), "r"(a[3]), "r"(b[0]), "r"(b[1]));
}

__device__ __forceinline__ void ldsm4(uint32_t* r, uint32_t addr) {
    asm volatile("ldmatrix.sync.aligned.m8n8.x4.shared.b16 {%0,%1,%2,%3}, [%4];"
        : "=r"(r[0]), "=r"(r[1]), "=r"(r[2]), "=r"(r[3]) : "r"(addr));
}

// ---------------------------------------------------------------------------
// tf32 mma.sync GEMM, 4-stage single-sync pipeline (prefetch distance 3).
// C[M,N] = A[M,K] @ Bt[N,K]^T (+bias); 128x128x16 CTA tile, 256 threads,
// 8 warps (2x4), warp tile 64x32, ldmatrix fragments.
// A is raw fp32 (rounded to tf32 in-register); Bt must be pre-rounded.
// ---------------------------------------------------------------------------
#define ASTR 20                          // floats per smem row (16 + 4 pad)
#define STAGE_FLOATS (2 * 128 * ASTR)    // A tile then B tile
#define STAGE_BYTES (STAGE_FLOATS * 4)   // 20480
#define NSTAGE 4
#define GEMM_SMEM (NSTAGE * STAGE_BYTES) // 81920

__global__ __launch_bounds__(256) void tf32_mma_gemm(
    const float* __restrict__ A, const float* __restrict__ Bt,
    const float* __restrict__ bias, float* __restrict__ C,
    int N, int K)
{
    extern __shared__ __align__(128) float smf[];
    const uint32_t sbase = (uint32_t)__cvta_generic_to_shared(smf);

    const int tid = threadIdx.x, lane = tid & 31, w = tid >> 5;
    const int wm = w & 1, wn = w >> 1;           // warp 2x4 grid
    const int g = lane >> 2, tig = lane & 3;
    const int bm = blockIdx.y * 128, bn = blockIdx.x * 128;

    // cp.async mapping
    const int lm0 = tid >> 2;            // 0..63
    const int lkq = (tid & 3) * 4;       // 0,4,8,12
    const float* Ag0 = A + (size_t)(bm + lm0) * K + lkq;
    const float* Ag1 = Ag0 + (size_t)64 * K;
    const float* Bg0 = Bt + (size_t)(bn + lm0) * K + lkq;
    const float* Bg1 = Bg0 + (size_t)64 * K;
    const uint32_t offA0 = (lm0 * ASTR + lkq) * 4;
    const uint32_t offA1 = ((lm0 + 64) * ASTR + lkq) * 4;
    const uint32_t offB0 = 128 * ASTR * 4 + offA0;
    const uint32_t offB1 = 128 * ASTR * 4 + offA1;

    // ldmatrix per-lane offsets
    const uint32_t a_lrow = (lane & 7) + ((lane >> 3) & 1) * 8;
    const uint32_t a_lk = (lane >> 4) * 4;
    const uint32_t b_lrow = (lane & 7) + ((lane >> 4) & 1) * 8;
    const uint32_t b_lk = ((lane >> 3) & 1) * 4;

    const uint32_t aAddr0 = sbase + ((wm * 64 + a_lrow) * ASTR + a_lk) * 4;
    const uint32_t bAddr0 = sbase + (128 * ASTR + (wn * 32 + b_lrow) * ASTR + b_lk) * 4;

    const int nchunks = K / 16;

    // Prologue: chunks 0,1,2 into stages 0,1,2
#pragma unroll
    for (int s = 0; s < 3; s++) {
        uint32_t so = sbase + s * STAGE_BYTES;
        cp16(so + offA0, Ag0 + s * 16);
        cp16(so + offA1, Ag1 + s * 16);
        cp16(so + offB0, Bg0 + s * 16);
        cp16(so + offB1, Bg1 + s * 16);
        cp_commit();
    }

    float acc[4][4][4] = {};
    int cur = 0, nxt = 3;

    for (int c = 0; c < nchunks; c++) {
        cp_wait2();        // chunk c landed (<=2 newer groups pending)
        __syncthreads();   // chunk c visible; all warps done with stage (c-1)%4

        // Issue chunk c+3 into the just-freed stage
        if (c + 3 < nchunks) {
            uint32_t so = sbase + nxt * STAGE_BYTES;
            const int k0 = (c + 3) * 16;
            cp16(so + offA0, Ag0 + k0);
            cp16(so + offA1, Ag1 + k0);
            cp16(so + offB0, Bg0 + k0);
            cp16(so + offB1, Bg1 + k0);
        }
        cp_commit();
        nxt = (nxt + 1) & 3;

        const uint32_t st = cur * STAGE_BYTES;
        cur = (cur + 1) & 3;

#pragma unroll
        for (int ks = 0; ks < 16; ks += 8) {
            uint32_t afr[4][4];
#pragma unroll
            for (int i = 0; i < 4; i++) {
                ldsm4(afr[i], aAddr0 + st + (i * 16 * ASTR + ks) * 4);
                afr[i][0] = rnd_u32(afr[i][0]);
                afr[i][1] = rnd_u32(afr[i][1]);
                afr[i][2] = rnd_u32(afr[i][2]);
                afr[i][3] = rnd_u32(afr[i][3]);
            }
            uint32_t bfr[2][4];
#pragma unroll
            for (int jp = 0; jp < 2; jp++)
                ldsm4(bfr[jp], bAddr0 + st + (jp * 16 * ASTR + ks) * 4);
#pragma unroll
            for (int i = 0; i < 4; i++)
#pragma unroll
                for (int jp = 0; jp < 2; jp++) {
                    mma_tf32(acc[i][jp * 2],     afr[i], bfr[jp]);
                    mma_tf32(acc[i][jp * 2 + 1], afr[i], bfr[jp] + 2);
                }
        }
    }

#pragma unroll
    for (int i = 0; i < 4; i++) {
        const int r0 = bm + wm * 64 + i * 16 + g;
#pragma unroll
        for (int j = 0; j < 4; j++) {
            const int c0 = bn + wn * 32 + j * 8 + tig * 2;
            float bx = 0.f, by = 0.f;
            if (bias) { bx = bias[c0]; by = bias[c0 + 1]; }
            float2 o0 = make_float2(acc[i][j][0] + bx, acc[i][j][1] + by);
            float2 o1 = make_float2(acc[i][j][2] + bx, acc[i][j][3] + by);
            *(float2*)&C[(size_t)r0 * N + c0] = o0;
            *(float2*)&C[(size_t)(r0 + 8) * N + c0] = o1;
        }
    }
}

// ---------------------------------------------------------------------------
// Prep: transpose+round (src[K,N] -> dst[N,K])
// ---------------------------------------------------------------------------
__global__ __launch_bounds__(256) void transpose_round_kernel(
    const float* __restrict__ src, float* __restrict__ dst, int K, int N)
{
    __shared__ float t[32][33];
    int n0 = blockIdx.x * 32, k0 = blockIdx.y * 32;
    int x = threadIdx.x & 31, y = threadIdx.x >> 5;   // 32 x 8
#pragma unroll
    for (int i = 0; i < 4; i++)
        t[y + i * 8][x] = src[(size_t)(k0 + y + i * 8) * N + n0 + x];
    __syncthreads();
#pragma unroll
    for (int i = 0; i < 4; i++)
        dst[(size_t)(n0 + y + i * 8) * K + k0 + x] = to_tf32(t[x][y + i * 8]);
}

// ---------------------------------------------------------------------------
// RoPE (Q/K only, coalesced) + separate tiled V transpose.
// ---------------------------------------------------------------------------
__global__ __launch_bounds__(256) void rope_kernel(
    const float* __restrict__ qkv,
    float* __restrict__ Q, float* __restrict__ K)
{
    const int bt = blockIdx.x;
    const int b = bt >> 11;
    const int t = bt & 2047;
    const float* row = qkv + (size_t)bt * (3 * HDIM);
    const float LN1E4_OVER_32 = 0.28782313662425575f;  // ln(10000)/32

#pragma unroll
    for (int it = 0; it < 4; it++) {
        int idx = it * 256 + threadIdx.x;
        int h = idx >> 6;
        int d = idx & 63;
        const float* base = row + h * (3 * HD);
        float qv = base[d];
        float kv = base[HD + d];
        int fi = d & 31;
        float inv = expf(-(float)fi * LN1E4_OVER_32);
        float ang = (float)t * inv;
        float sv, cv;
        sincosf(ang, &sv, &cv);
        float qrot = (d < 32) ? -base[d + 32] : base[d - 32];
        float krot = (d < 32) ? -base[HD + d + 32] : base[HD + d - 32];
        int bh = b * NHEAD + h;
        size_t o = ((size_t)bh * T_SEQ + t) * HD + d;
        Q[o] = to_tf32((qv * cv + qrot * sv) * 0.125f);
        K[o] = to_tf32(kv * cv + krot * sv);
    }
}

// V slice of qkv -> Vt [bh][d][t], tf32-rounded, tiled transpose.
__global__ __launch_bounds__(256) void vtrans_kernel(
    const float* __restrict__ qkv, float* __restrict__ Vt)
{
    __shared__ float t[32][33];
    const int t0 = blockIdx.x * 32;
    const int d0 = blockIdx.y * 32;
    const int bh = blockIdx.z;
    const int b = bh >> 4, h = bh & 15;
    const int x = threadIdx.x & 31, y = threadIdx.x >> 5;

#pragma unroll
    for (int i = 0; i < 4; i++)
        t[y + i * 8][x] =
            qkv[(size_t)(b * T_SEQ + t0 + y + i * 8) * (3 * HDIM) + h * 192 + 128 + d0 + x];
    __syncthreads();
#pragma unroll
    for (int i = 0; i < 4; i++)
        Vt[((size_t)bh * HD + d0 + y + i * 8) * T_SEQ + t0 + x] = to_tf32(t[x][y + i * 8]);
}

// ---------------------------------------------------------------------------
// Flash attention with tf32 mma.sync + ldmatrix, pipelined K/V loads.
// qb is REVERSED so the heaviest CTAs (most key blocks) launch first.
// ---------------------------------------------------------------------------
#define AQS 68   // smem row stride (floats): conflict-free for ldmatrix
#define ATT_SMEM ((128 * AQS + 64 * AQS + 64 * AQS + 128 * AQS) * 4 + 64 * 4)

__global__ __launch_bounds__(256, 2) void attn_mma_kernel(
    const float* __restrict__ Q, const float* __restrict__ K,
    const float* __restrict__ Vt, const int* __restrict__ amask,
    float* __restrict__ out)
{
    extern __shared__ __align__(128) float s[];
    float* Qs  = s;                    // [128][AQS]
    float* Ks  = Qs + 128 * AQS;       // [64][AQS]   Ks[key][d]
    float* Vts = Ks + 64 * AQS;        // [64][AQS]   Vts[d][key]
    float* Ps  = Vts + 64 * AQS;       // [128][AQS]
    int* smask = (int*)(Ps + 128 * AQS);

    const uint32_t sb  = (uint32_t)__cvta_generic_to_shared(s);
    const uint32_t ksb = (uint32_t)__cvta_generic_to_shared(Ks);
    const uint32_t vsb = (uint32_t)__cvta_generic_to_shared(Vts);
    const uint32_t psb = (uint32_t)__cvta_generic_to_shared(Ps);

    const int tid = threadIdx.x, lane = tid & 31, w = tid >> 5;
    const int g = lane >> 2, tig = lane & 3;
    const int qb = gridDim.x - 1 - blockIdx.x;   // heavy CTAs first
    const int bh = blockIdx.y;
    const int b = bh >> 4, h = bh & 15;

    // ldmatrix per-lane offsets
    const uint32_t a_lrow = (lane & 7) + ((lane >> 3) & 1) * 8;
    const uint32_t a_lk = (lane >> 4) * 4;
    const uint32_t b_lrow = (lane & 7) + ((lane >> 4) & 1) * 8;
    const uint32_t b_lk = ((lane >> 3) & 1) * 4;

    const uint32_t qAddr0 = sb  + ((w * 16 + a_lrow) * AQS + a_lk) * 4;
    const uint32_t pAddr0 = psb + ((w * 16 + a_lrow) * AQS + a_lk) * 4;
    const uint32_t kAddr0 = ksb + (b_lrow * AQS + b_lk) * 4;
    const uint32_t vAddr0 = vsb + (b_lrow * AQS + b_lk) * 4;

    // Prologue: Q tile (group 0) + K(0) (group 1)
    const float* Qg = Q + ((size_t)bh * T_SEQ + qb * 128) * HD;
#pragma unroll
    for (int it = 0; it < 8; it++) {
        int idx = it * 256 + tid;
        int r = idx >> 4, c4 = (idx & 15) << 2;
        cp16(sb + (r * AQS + c4) * 4, Qg + r * HD + c4);
    }
    cp_commit();

    const float* Kbase = K + (size_t)bh * T_SEQ * HD;
    const float* Vbase = Vt + (size_t)bh * HD * T_SEQ;

    {
        const float* Kg = Kbase;   // jb = 0
#pragma unroll
        for (int it = 0; it < 4; it++) {
            int idx = it * 256 + tid;
            int r = idx >> 4, c4 = (idx & 15) << 2;
            cp16(ksb + (r * AQS + c4) * 4, Kg + r * HD + c4);
        }
    }
    cp_commit();

    float accO[8][4] = {};
    float m0 = -1e30f, m1 = -1e30f, l0 = 0.f, l1 = 0.f;

    const int qrow0 = qb * 128 + w * 16 + g;
    const int qrow1 = qrow0 + 8;
    const int nkb = 2 * qb + 2;

    for (int jb = 0; jb < nkb; jb++) {
        // 1) K(jb) (and everything older) landed
        cp_wait0();
        __syncthreads();   // K visible; all warps past PV(jb-1) -> Vts free

        // 2) issue V(jb) loads + mask
        {
            const float* Vg = Vbase + jb * 64;
#pragma unroll
            for (int it = 0; it < 4; it++) {
                int idx = it * 256 + tid;
                int r = idx >> 4, c4 = (idx & 15) << 2;
                cp16(vsb + (r * AQS + c4) * 4, Vg + (size_t)r * T_SEQ + c4);
            }
        }
        if (tid < 64) smask[tid] = amask[b * T_SEQ + jb * 64 + tid];
        cp_commit();       // group: V(jb)

        // 3) S = Q_tile @ K_tile^T
        float sacc[8][4];
#pragma unroll
        for (int j = 0; j < 8; j++)
            sacc[j][0] = sacc[j][1] = sacc[j][2] = sacc[j][3] = 0.f;
#pragma unroll
        for (int ks = 0; ks < 8; ks++) {
            uint32_t af[4];
            ldsm4(af, qAddr0 + ks * 32);
#pragma unroll
            for (int jp = 0; jp < 4; jp++) {
                uint32_t bf[4];
                ldsm4(bf, kAddr0 + (jp * 16 * AQS + ks * 8) * 4);
                mma_tf32(sacc[jp * 2],     af, bf);
                mma_tf32(sacc[jp * 2 + 1], af, bf + 2);
            }
        }

        __syncthreads();   // all warps done reading Ks; smask visible

        // 4) issue K(jb+1) loads (hidden behind softmax + PV)
        if (jb + 1 < nkb) {
            const float* Kg = Kbase + (size_t)(jb + 1) * 64 * HD;
#pragma unroll
            for (int it = 0; it < 4; it++) {
                int idx = it * 256 + tid;
                int r = idx >> 4, c4 = (idx & 15) << 2;
                cp16(ksb + (r * AQS + c4) * 4, Kg + r * HD + c4);
            }
        }
        cp_commit();       // group: K(jb+1) (possibly empty)

        // 5) mask + online softmax (registers)
        float mx0 = m0, mx1 = m1;
#pragma unroll
        for (int j = 0; j < 8; j++) {
            int c = j * 8 + 2 * tig;
            int colg = jb * 64 + c;
            bool v0 = smask[c]     && (colg     <= qrow0);
            bool v1 = smask[c + 1] && (colg + 1 <= qrow0);
            bool v2 = smask[c]     && (colg     <= qrow1);
            bool v3 = smask[c + 1] && (colg + 1 <= qrow1);
            sacc[j][0] = v0 ? sacc[j][0] : -1e30f;
            sacc[j][1] = v1 ? sacc[j][1] : -1e30f;
            sacc[j][2] = v2 ? sacc[j][2] : -1e30f;
            sacc[j][3] = v3 ? sacc[j][3] : -1e30f;
            mx0 = fmaxf(mx0, fmaxf(sacc[j][0], sacc[j][1]));
            mx1 = fmaxf(mx1, fmaxf(sacc[j][2], sacc[j][3]));
        }
        mx0 = fmaxf(mx0, __shfl_xor_sync(0xffffffff, mx0, 1));
        mx0 = fmaxf(mx0, __shfl_xor_sync(0xffffffff, mx0, 2));
        mx1 = fmaxf(mx1, __shfl_xor_sync(0xffffffff, mx1, 1));
        mx1 = fmaxf(mx1, __shfl_xor_sync(0xffffffff, mx1, 2));
        float corr0 = __expf(m0 - mx0);
        float corr1 = __expf(m1 - mx1);
        m0 = mx0; m1 = mx1;

        float sum0 = 0.f, sum1 = 0.f;
        float* prow0 = Ps + (w * 16 + g) * AQS;
        float* prow1 = prow0 + 8 * AQS;
#pragma unroll
        for (int j = 0; j < 8; j++) {
            int c = j * 8 + 2 * tig;
            float p0 = to_tf32(__expf(sacc[j][0] - mx0));
            float p1 = to_tf32(__expf(sacc[j][1] - mx0));
            float p2 = to_tf32(__expf(sacc[j][2] - mx1));
            float p3 = to_tf32(__expf(sacc[j][3] - mx1));
            sum0 += p0 + p1;
            sum1 += p2 + p3;
            *(float2*)&prow0[c] = make_float2(p0, p1);
            *(float2*)&prow1[c] = make_float2(p2, p3);
        }
        sum0 += __shfl_xor_sync(0xffffffff, sum0, 1);
        sum0 += __shfl_xor_sync(0xffffffff, sum0, 2);
        sum1 += __shfl_xor_sync(0xffffffff, sum1, 1);
        sum1 += __shfl_xor_sync(0xffffffff, sum1, 2);
        l0 = l0 * corr0 + sum0;
        l1 = l1 * corr1 + sum1;

#pragma unroll
        for (int j = 0; j < 8; j++) {
            accO[j][0] *= corr0; accO[j][1] *= corr0;
            accO[j][2] *= corr1; accO[j][3] *= corr1;
        }
        __syncwarp();

        // 6) wait V(jb) (K(jb+1) may stay in flight), then PV
        cp_wait1();
        __syncthreads();   // V visible to all warps

#pragma unroll
        for (int ks = 0; ks < 8; ks++) {
            uint32_t pa[4];
            ldsm4(pa, pAddr0 + ks * 32);
#pragma unroll
            for (int jp = 0; jp < 4; jp++) {
                uint32_t bf[4];
                ldsm4(bf, vAddr0 + (jp * 16 * AQS + ks * 8) * 4);
                mma_tf32(accO[jp * 2],     pa, bf);
                mma_tf32(accO[jp * 2 + 1], pa, bf + 2);
            }
        }
    }

    // ---- epilogue (raw fp32; out-GEMM rounds its A fragments itself) ----
    float inv0 = 1.f / l0, inv1 = 1.f / l1;
    const int r0 = b * T_SEQ + qb * 128 + w * 16 + g;
#pragma unroll
    for (int j = 0; j < 8; j++) {
        int c = h * HD + j * 8 + 2 * tig;
        float2 o0 = make_float2(accO[j][0] * inv0, accO[j][1] * inv0);
        float2 o1 = make_float2(accO[j][2] * inv1, accO[j][3] * inv1);
        *(float2*)&out[(size_t)r0 * HDIM + c] = o0;
        *(float2*)&out[(size_t)(r0 + 8) * HDIM + c] = o1;
    }
}

// ---------------------------------------------------------------------------
// Launch
// ---------------------------------------------------------------------------
extern "C" void kernel_launch(void* const* d_in, const int* in_sizes, int n_in,
                              void* d_out, int out_size)
{
    const float* hidden = (const float*)d_in[0];
    const int*   amask  = (const int*)d_in[1];
    const float* w_qkv  = (const float*)d_in[2];
    const float* b_qkv  = (const float*)d_in[3];
    const float* w_out  = (const float*)d_in[4];
    float* out = (float*)d_out;

    float *qkv, *Q, *K, *V, *attn, *Bt1, *Bt2;
    cudaGetSymbolAddress((void**)&qkv,  g_qkv);
    cudaGetSymbolAddress((void**)&Q,    g_Q);
    cudaGetSymbolAddress((void**)&K,    g_K);
    cudaGetSymbolAddress((void**)&V,    g_V);
    cudaGetSymbolAddress((void**)&attn, g_attn);
    cudaGetSymbolAddress((void**)&Bt1,  g_Bt1);
    cudaGetSymbolAddress((void**)&Bt2,  g_Bt2);

    cudaFuncSetAttribute(attn_mma_kernel, cudaFuncAttributeMaxDynamicSharedMemorySize,
                         ATT_SMEM);
    cudaFuncSetAttribute(tf32_mma_gemm, cudaFuncAttributeMaxDynamicSharedMemorySize,
                         GEMM_SMEM);

    // 0) transpose+round weights
    transpose_round_kernel<<<dim3(3 * HDIM / 32, HDIM / 32), 256>>>(w_qkv, Bt1, HDIM, 3 * HDIM);
    transpose_round_kernel<<<dim3(HDIM / 32, HDIM / 32), 256>>>(w_out, Bt2, HDIM, HDIM);

    // 1) qkv = hidden @ w_qkv + b_qkv (tf32 mma.sync, 4-stage single-sync)
    tf32_mma_gemm<<<dim3(3 * HDIM / 128, MROWS / 128), 256, GEMM_SMEM>>>(
        hidden, Bt1, b_qkv, qkv, 3 * HDIM, HDIM);

    // 2) RoPE (Q/K) + V transpose
    rope_kernel<<<MROWS, 256>>>(qkv, Q, K);
    vtrans_kernel<<<dim3(T_SEQ / 32, HD / 32, BATCH * NHEAD), 256>>>(qkv, V);

    // 3) tf32 mma flash attention -> attn [B,T,H]
    attn_mma_kernel<<<dim3(T_SEQ / 128, BATCH * NHEAD), 256, ATT_SMEM>>>(
        Q, K, V, amask, attn);

    // 4) out = attn @ w_out (tf32 mma.sync, 4-stage single-sync)
    tf32_mma_gemm<<<dim3(HDIM / 128, MROWS / 128), 256, GEMM_SMEM>>>(
        attn, Bt2, nullptr, out, HDIM, HDIM);
}

// round 9
// speedup vs baseline: 1.0560x; 1.0278x over previous
#include <cuda_runtime.h>
#include <cstdint>
#include <cstddef>

// Problem constants
#define T_SEQ  2048
#define NHEAD  16
#define HDIM   1024
#define HD     64
#define BATCH  2
#define MROWS  (BATCH * T_SEQ)   // 4096

// Scratch (device globals; no allocations allowed)
__device__ float g_qkv[MROWS * 3 * HDIM];
__device__ float g_Q[BATCH * NHEAD * T_SEQ * HD];    // [bh][t][d], tf32, pre-scaled
__device__ float g_K[BATCH * NHEAD * T_SEQ * HD];    // [bh][t][d], tf32
__device__ float g_V[BATCH * NHEAD * T_SEQ * HD];    // [bh][d][t]  (TRANSPOSED), tf32
__device__ float g_attn[MROWS * HDIM];               // tf32-rounded attention output
__device__ float g_Bt1[3 * HDIM * HDIM];             // w_qkv^T rounded [3072,1024]
__device__ float g_Bt2[HDIM * HDIM];                 // w_out^T rounded [1024,1024]

// ---------------------------------------------------------------------------
// Helpers
// ---------------------------------------------------------------------------
__device__ __forceinline__ float to_tf32(float x) {
    uint32_t u;
    asm("cvt.rna.tf32.f32 %0, %1;" : "=r"(u) : "f"(x));
    return __uint_as_float(u);
}

__device__ __forceinline__ uint32_t rnd_u32(uint32_t x) {
    uint32_t u;
    asm("cvt.rna.tf32.f32 %0, %1;" : "=r"(u) : "r"(x));
    return u;
}

__device__ __forceinline__ void cp16(uint32_t dst, const void* src) {
    asm volatile("cp.async.cg.shared.global [%0], [%1], 16;\n" :: "r"(dst), "l"(src));
}
__device__ __forceinline__ void cp_commit() {
    asm volatile("cp.async.commit_group;\n");
}
__device__ __forceinline__ void cp_wait3() {
    asm volatile("cp.async.wait_group 3;\n");
}
__device__ __forceinline__ void cp_wait1() {
    asm volatile("cp.async.wait_group 1;\n");
}
__device__ __forceinline__ void cp_wait0() {
    asm volatile("cp.async.wait_group 0;\n");
}

__device__ __forceinline__ void mma_tf32(float* c, const uint32_t* a, const uint32_t* b) {
    asm volatile(
        "mma.sync.aligned.m16n8k8.row.col.f32.tf32.tf32.f32 "
        "{%0,%1,%2,%3}, {%4,%5,%6,%7}, {%8,%9}, {%0,%1,%2,%3};"
        : "+f"(c[0]), "+f"(c[1]), "+f"(c[2]), "+f"(c[3])
        : "r"(a[0]), "r"(a[1]), "r"(a[2]), "r"(a[3]), "r"(b[0]), "r"(b[1]));
}

__device__ __forceinline__ void ldsm4(uint32_t* r, uint32_t addr) {
    asm volatile("ldmatrix.sync.aligned.m8n8.x4.shared.b16 {%0,%1,%2,%3}, [%4];"
        : "=r"(r[0]), "=r"(r[1]), "=r"(r[2]), "=r"(r[3]) : "r"(addr));
}

// ---------------------------------------------------------------------------
// tf32 mma.sync GEMM — round-5 proven mainloop (4-stage, wait3, distance 4),
// ldmatrix fragments, optional in-register tf32 rounding of A (RND).
// C[M,N] = A[M,K] @ Bt[N,K]^T (+bias); 128x128x16 CTA tile, 256 threads.
// ---------------------------------------------------------------------------
#define ASTR 20                          // floats per smem row (16 + 4 pad)
#define STAGE_FLOATS (2 * 128 * ASTR)    // A tile then B tile
#define STAGE_BYTES (STAGE_FLOATS * 4)   // 20480
#define GEMM_SMEM (4 * STAGE_BYTES)      // 81920

template<bool RND>
__global__ __launch_bounds__(256) void tf32_mma_gemm(
    const float* __restrict__ A, const float* __restrict__ Bt,
    const float* __restrict__ bias, float* __restrict__ C,
    int N, int K)
{
    extern __shared__ __align__(128) float smf[];
    const uint32_t sbase = (uint32_t)__cvta_generic_to_shared(smf);

    const int tid = threadIdx.x, lane = tid & 31, w = tid >> 5;
    const int wm = w & 1, wn = w >> 1;           // warp 2x4 grid
    const int g = lane >> 2, tig = lane & 3;
    const int bm = blockIdx.y * 128, bn = blockIdx.x * 128;

    // cp.async mapping
    const int lm0 = tid >> 2;            // 0..63
    const int lkq = (tid & 3) * 4;       // 0,4,8,12
    const float* Ag0 = A + (size_t)(bm + lm0) * K + lkq;
    const float* Ag1 = Ag0 + (size_t)64 * K;
    const float* Bg0 = Bt + (size_t)(bn + lm0) * K + lkq;
    const float* Bg1 = Bg0 + (size_t)64 * K;
    const uint32_t offA0 = (lm0 * ASTR + lkq) * 4;
    const uint32_t offA1 = ((lm0 + 64) * ASTR + lkq) * 4;
    const uint32_t offB0 = 128 * ASTR * 4 + offA0;
    const uint32_t offB1 = 128 * ASTR * 4 + offA1;

    // ldmatrix per-lane offsets
    const uint32_t a_lrow = (lane & 7) + ((lane >> 3) & 1) * 8;
    const uint32_t a_lk = (lane >> 4) * 4;
    const uint32_t b_lrow = (lane & 7) + ((lane >> 4) & 1) * 8;
    const uint32_t b_lk = ((lane >> 3) & 1) * 4;

    const uint32_t aAddr0 = sbase + ((wm * 64 + a_lrow) * ASTR + a_lk) * 4;
    const uint32_t bAddr0 = sbase + (128 * ASTR + (wn * 32 + b_lrow) * ASTR + b_lk) * 4;

    const int nchunks = K / 16;

    // Prologue: fill 4 stages (distance 4)
#pragma unroll
    for (int s = 0; s < 4; s++) {
        uint32_t so = sbase + s * STAGE_BYTES;
        cp16(so + offA0, Ag0 + s * 16);
        cp16(so + offA1, Ag1 + s * 16);
        cp16(so + offB0, Bg0 + s * 16);
        cp16(so + offB1, Bg1 + s * 16);
        cp_commit();
    }

    float acc[4][4][4] = {};

    for (int c = 0; c < nchunks; c++) {
        cp_wait3();
        __syncthreads();

        const uint32_t st = (c & 3) * STAGE_BYTES;

#pragma unroll
        for (int ks = 0; ks < 16; ks += 8) {
            uint32_t afr[4][4];
#pragma unroll
            for (int i = 0; i < 4; i++) {
                ldsm4(afr[i], aAddr0 + st + (i * 16 * ASTR + ks) * 4);
                if (RND) {
                    afr[i][0] = rnd_u32(afr[i][0]);
                    afr[i][1] = rnd_u32(afr[i][1]);
                    afr[i][2] = rnd_u32(afr[i][2]);
                    afr[i][3] = rnd_u32(afr[i][3]);
                }
            }
            uint32_t bfr[2][4];
#pragma unroll
            for (int jp = 0; jp < 2; jp++)
                ldsm4(bfr[jp], bAddr0 + st + (jp * 16 * ASTR + ks) * 4);
#pragma unroll
            for (int i = 0; i < 4; i++)
#pragma unroll
                for (int jp = 0; jp < 2; jp++) {
                    mma_tf32(acc[i][jp * 2],     afr[i], bfr[jp]);
                    mma_tf32(acc[i][jp * 2 + 1], afr[i], bfr[jp] + 2);
                }
        }
        __syncthreads();

        if (c + 4 < nchunks) {
            uint32_t so = sbase + (c & 3) * STAGE_BYTES;
            const int k0 = (c + 4) * 16;
            cp16(so + offA0, Ag0 + k0);
            cp16(so + offA1, Ag1 + k0);
            cp16(so + offB0, Bg0 + k0);
            cp16(so + offB1, Bg1 + k0);
        }
        cp_commit();
    }

#pragma unroll
    for (int i = 0; i < 4; i++) {
        const int r0 = bm + wm * 64 + i * 16 + g;
#pragma unroll
        for (int j = 0; j < 4; j++) {
            const int c0 = bn + wn * 32 + j * 8 + tig * 2;
            float bx = 0.f, by = 0.f;
            if (bias) { bx = bias[c0]; by = bias[c0 + 1]; }
            float2 o0 = make_float2(acc[i][j][0] + bx, acc[i][j][1] + by);
            float2 o1 = make_float2(acc[i][j][2] + bx, acc[i][j][3] + by);
            *(float2*)&C[(size_t)r0 * N + c0] = o0;
            *(float2*)&C[(size_t)(r0 + 8) * N + c0] = o1;
        }
    }
}

// ---------------------------------------------------------------------------
// Prep: transpose+round (src[K,N] -> dst[N,K])
// ---------------------------------------------------------------------------
__global__ __launch_bounds__(256) void transpose_round_kernel(
    const float* __restrict__ src, float* __restrict__ dst, int K, int N)
{
    __shared__ float t[32][33];
    int n0 = blockIdx.x * 32, k0 = blockIdx.y * 32;
    int x = threadIdx.x & 31, y = threadIdx.x >> 5;   // 32 x 8
#pragma unroll
    for (int i = 0; i < 4; i++)
        t[y + i * 8][x] = src[(size_t)(k0 + y + i * 8) * N + n0 + x];
    __syncthreads();
#pragma unroll
    for (int i = 0; i < 4; i++)
        dst[(size_t)(n0 + y + i * 8) * K + k0 + x] = to_tf32(t[x][y + i * 8]);
}

// ---------------------------------------------------------------------------
// RoPE (Q/K only, coalesced) + separate tiled V transpose.
// ---------------------------------------------------------------------------
__global__ __launch_bounds__(256) void rope_kernel(
    const float* __restrict__ qkv,
    float* __restrict__ Q, float* __restrict__ K)
{
    const int bt = blockIdx.x;
    const int b = bt >> 11;
    const int t = bt & 2047;
    const float* row = qkv + (size_t)bt * (3 * HDIM);
    const float LN1E4_OVER_32 = 0.28782313662425575f;  // ln(10000)/32

#pragma unroll
    for (int it = 0; it < 4; it++) {
        int idx = it * 256 + threadIdx.x;
        int h = idx >> 6;
        int d = idx & 63;
        const float* base = row + h * (3 * HD);
        float qv = base[d];
        float kv = base[HD + d];
        int fi = d & 31;
        float inv = expf(-(float)fi * LN1E4_OVER_32);
        float ang = (float)t * inv;
        float sv, cv;
        sincosf(ang, &sv, &cv);
        float qrot = (d < 32) ? -base[d + 32] : base[d - 32];
        float krot = (d < 32) ? -base[HD + d + 32] : base[HD + d - 32];
        int bh = b * NHEAD + h;
        size_t o = ((size_t)bh * T_SEQ + t) * HD + d;
        Q[o] = to_tf32((qv * cv + qrot * sv) * 0.125f);
        K[o] = to_tf32(kv * cv + krot * sv);
    }
}

// V slice of qkv -> Vt [bh][d][t], tf32-rounded, tiled transpose.
__global__ __launch_bounds__(256) void vtrans_kernel(
    const float* __restrict__ qkv, float* __restrict__ Vt)
{
    __shared__ float t[32][33];
    const int t0 = blockIdx.x * 32;
    const int d0 = blockIdx.y * 32;
    const int bh = blockIdx.z;
    const int b = bh >> 4, h = bh & 15;
    const int x = threadIdx.x & 31, y = threadIdx.x >> 5;

#pragma unroll
    for (int i = 0; i < 4; i++)
        t[y + i * 8][x] =
            qkv[(size_t)(b * T_SEQ + t0 + y + i * 8) * (3 * HDIM) + h * 192 + 128 + d0 + x];
    __syncthreads();
#pragma unroll
    for (int i = 0; i < 4; i++)
        Vt[((size_t)bh * HD + d0 + y + i * 8) * T_SEQ + t0 + x] = to_tf32(t[x][y + i * 8]);
}

// ---------------------------------------------------------------------------
// Flash attention with tf32 mma.sync + ldmatrix, pipelined K/V loads,
// LPT qb-reversal, and fully-padded key-block skipping.
// ---------------------------------------------------------------------------
#define AQS 68   // smem row stride (floats): conflict-free for ldmatrix
#define ATT_SMEM ((128 * AQS + 64 * AQS + 64 * AQS + 128 * AQS) * 4 + 64 * 4)

__global__ __launch_bounds__(256, 2) void attn_mma_kernel(
    const float* __restrict__ Q, const float* __restrict__ K,
    const float* __restrict__ Vt, const int* __restrict__ amask,
    float* __restrict__ out)
{
    extern __shared__ __align__(128) float s[];
    float* Qs  = s;                    // [128][AQS]
    float* Ks  = Qs + 128 * AQS;       // [64][AQS]   Ks[key][d]
    float* Vts = Ks + 64 * AQS;        // [64][AQS]   Vts[d][key]
    float* Ps  = Vts + 64 * AQS;       // [128][AQS]
    int* smask = (int*)(Ps + 128 * AQS);

    const uint32_t sb  = (uint32_t)__cvta_generic_to_shared(s);
    const uint32_t ksb = (uint32_t)__cvta_generic_to_shared(Ks);
    const uint32_t vsb = (uint32_t)__cvta_generic_to_shared(Vts);
    const uint32_t psb = (uint32_t)__cvta_generic_to_shared(Ps);

    const int tid = threadIdx.x, lane = tid & 31, w = tid >> 5;
    const int g = lane >> 2, tig = lane & 3;
    const int qb = gridDim.x - 1 - blockIdx.x;   // heavy CTAs first
    const int bh = blockIdx.y;
    const int b = bh >> 4, h = bh & 15;

    // Live key-block count (padding is a prefix mask: block live iff first elem set)
    int livev = (amask[b * T_SEQ + lane * 64] != 0) ? 1 : 0;
    unsigned liveb = __ballot_sync(0xffffffff, livev);
    const int nlive = __popc(liveb);

    // ldmatrix per-lane offsets
    const uint32_t a_lrow = (lane & 7) + ((lane >> 3) & 1) * 8;
    const uint32_t a_lk = (lane >> 4) * 4;
    const uint32_t b_lrow = (lane & 7) + ((lane >> 4) & 1) * 8;
    const uint32_t b_lk = ((lane >> 3) & 1) * 4;

    const uint32_t qAddr0 = sb  + ((w * 16 + a_lrow) * AQS + a_lk) * 4;
    const uint32_t pAddr0 = psb + ((w * 16 + a_lrow) * AQS + a_lk) * 4;
    const uint32_t kAddr0 = ksb + (b_lrow * AQS + b_lk) * 4;
    const uint32_t vAddr0 = vsb + (b_lrow * AQS + b_lk) * 4;

    // Prologue: Q tile (group 0) + K(0) (group 1)
    const float* Qg = Q + ((size_t)bh * T_SEQ + qb * 128) * HD;
#pragma unroll
    for (int it = 0; it < 8; it++) {
        int idx = it * 256 + tid;
        int r = idx >> 4, c4 = (idx & 15) << 2;
        cp16(sb + (r * AQS + c4) * 4, Qg + r * HD + c4);
    }
    cp_commit();

    const float* Kbase = K + (size_t)bh * T_SEQ * HD;
    const float* Vbase = Vt + (size_t)bh * HD * T_SEQ;

    {
        const float* Kg = Kbase;   // jb = 0
#pragma unroll
        for (int it = 0; it < 4; it++) {
            int idx = it * 256 + tid;
            int r = idx >> 4, c4 = (idx & 15) << 2;
            cp16(ksb + (r * AQS + c4) * 4, Kg + r * HD + c4);
        }
    }
    cp_commit();

    float accO[8][4] = {};
    float m0 = -1e30f, m1 = -1e30f, l0 = 0.f, l1 = 0.f;

    const int qrow0 = qb * 128 + w * 16 + g;
    const int qrow1 = qrow0 + 8;
    const int nkb = 2 * qb + 2;
    const int jb_end = (nkb < nlive) ? nkb : nlive;   // skip fully-padded blocks

    for (int jb = 0; jb < jb_end; jb++) {
        // 1) K(jb) (and everything older) landed
        cp_wait0();
        __syncthreads();   // K visible; all warps past PV(jb-1) -> Vts free

        // 2) issue V(jb) loads + mask
        {
            const float* Vg = Vbase + jb * 64;
#pragma unroll
            for (int it = 0; it < 4; it++) {
                int idx = it * 256 + tid;
                int r = idx >> 4, c4 = (idx & 15) << 2;
                cp16(vsb + (r * AQS + c4) * 4, Vg + (size_t)r * T_SEQ + c4);
            }
        }
        if (tid < 64) smask[tid] = amask[b * T_SEQ + jb * 64 + tid];
        cp_commit();       // group: V(jb)

        // 3) S = Q_tile @ K_tile^T
        float sacc[8][4];
#pragma unroll
        for (int j = 0; j < 8; j++)
            sacc[j][0] = sacc[j][1] = sacc[j][2] = sacc[j][3] = 0.f;
#pragma unroll
        for (int ks = 0; ks < 8; ks++) {
            uint32_t af[4];
            ldsm4(af, qAddr0 + ks * 32);
#pragma unroll
            for (int jp = 0; jp < 4; jp++) {
                uint32_t bf[4];
                ldsm4(bf, kAddr0 + (jp * 16 * AQS + ks * 8) * 4);
                mma_tf32(sacc[jp * 2],     af, bf);
                mma_tf32(sacc[jp * 2 + 1], af, bf + 2);
            }
        }

        __syncthreads();   // all warps done reading Ks; smask visible

        // 4) issue K(jb+1) loads (hidden behind softmax + PV)
        if (jb + 1 < jb_end) {
            const float* Kg = Kbase + (size_t)(jb + 1) * 64 * HD;
#pragma unroll
            for (int it = 0; it < 4; it++) {
                int idx = it * 256 + tid;
                int r = idx >> 4, c4 = (idx & 15) << 2;
                cp16(ksb + (r * AQS + c4) * 4, Kg + r * HD + c4);
            }
        }
        cp_commit();       // group: K(jb+1) (possibly empty)

        // 5) mask + online softmax (registers)
        float mx0 = m0, mx1 = m1;
#pragma unroll
        for (int j = 0; j < 8; j++) {
            int c = j * 8 + 2 * tig;
            int colg = jb * 64 + c;
            bool v0 = smask[c]     && (colg     <= qrow0);
            bool v1 = smask[c + 1] && (colg + 1 <= qrow0);
            bool v2 = smask[c]     && (colg     <= qrow1);
            bool v3 = smask[c + 1] && (colg + 1 <= qrow1);
            sacc[j][0] = v0 ? sacc[j][0] : -1e30f;
            sacc[j][1] = v1 ? sacc[j][1] : -1e30f;
            sacc[j][2] = v2 ? sacc[j][2] : -1e30f;
            sacc[j][3] = v3 ? sacc[j][3] : -1e30f;
            mx0 = fmaxf(mx0, fmaxf(sacc[j][0], sacc[j][1]));
            mx1 = fmaxf(mx1, fmaxf(sacc[j][2], sacc[j][3]));
        }
        mx0 = fmaxf(mx0, __shfl_xor_sync(0xffffffff, mx0, 1));
        mx0 = fmaxf(mx0, __shfl_xor_sync(0xffffffff, mx0, 2));
        mx1 = fmaxf(mx1, __shfl_xor_sync(0xffffffff, mx1, 1));
        mx1 = fmaxf(mx1, __shfl_xor_sync(0xffffffff, mx1, 2));
        float corr0 = __expf(m0 - mx0);
        float corr1 = __expf(m1 - mx1);
        m0 = mx0; m1 = mx1;

        float sum0 = 0.f, sum1 = 0.f;
        float* prow0 = Ps + (w * 16 + g) * AQS;
        float* prow1 = prow0 + 8 * AQS;
#pragma unroll
        for (int j = 0; j < 8; j++) {
            int c = j * 8 + 2 * tig;
            float p0 = to_tf32(__expf(sacc[j][0] - mx0));
            float p1 = to_tf32(__expf(sacc[j][1] - mx0));
            float p2 = to_tf32(__expf(sacc[j][2] - mx1));
            float p3 = to_tf32(__expf(sacc[j][3] - mx1));
            sum0 += p0 + p1;
            sum1 += p2 + p3;
            *(float2*)&prow0[c] = make_float2(p0, p1);
            *(float2*)&prow1[c] = make_float2(p2, p3);
        }
        sum0 += __shfl_xor_sync(0xffffffff, sum0, 1);
        sum0 += __shfl_xor_sync(0xffffffff, sum0, 2);
        sum1 += __shfl_xor_sync(0xffffffff, sum1, 1);
        sum1 += __shfl_xor_sync(0xffffffff, sum1, 2);
        l0 = l0 * corr0 + sum0;
        l1 = l1 * corr1 + sum1;

#pragma unroll
        for (int j = 0; j < 8; j++) {
            accO[j][0] *= corr0; accO[j][1] *= corr0;
            accO[j][2] *= corr1; accO[j][3] *= corr1;
        }
        __syncwarp();

        // 6) wait V(jb) (K(jb+1) may stay in flight), then PV
        cp_wait1();
        __syncthreads();   // V visible to all warps

#pragma unroll
        for (int ks = 0; ks < 8; ks++) {
            uint32_t pa[4];
            ldsm4(pa, pAddr0 + ks * 32);
#pragma unroll
            for (int jp = 0; jp < 4; jp++) {
                uint32_t bf[4];
                ldsm4(bf, vAddr0 + (jp * 16 * AQS + ks * 8) * 4);
                mma_tf32(accO[jp * 2],     pa, bf);
                mma_tf32(accO[jp * 2 + 1], pa, bf + 2);
            }
        }
    }

    // ---- epilogue (tf32-rounded; out-GEMM runs RND=false) ----
    float inv0 = 1.f / l0, inv1 = 1.f / l1;
    const int r0 = b * T_SEQ + qb * 128 + w * 16 + g;
#pragma unroll
    for (int j = 0; j < 8; j++) {
        int c = h * HD + j * 8 + 2 * tig;
        float2 o0 = make_float2(to_tf32(accO[j][0] * inv0), to_tf32(accO[j][1] * inv0));
        float2 o1 = make_float2(to_tf32(accO[j][2] * inv1), to_tf32(accO[j][3] * inv1));
        *(float2*)&out[(size_t)r0 * HDIM + c] = o0;
        *(float2*)&out[(size_t)(r0 + 8) * HDIM + c] = o1;
    }
}

// ---------------------------------------------------------------------------
// Launch
// ---------------------------------------------------------------------------
extern "C" void kernel_launch(void* const* d_in, const int* in_sizes, int n_in,
                              void* d_out, int out_size)
{
    const float* hidden = (const float*)d_in[0];
    const int*   amask  = (const int*)d_in[1];
    const float* w_qkv  = (const float*)d_in[2];
    const float* b_qkv  = (const float*)d_in[3];
    const float* w_out  = (const float*)d_in[4];
    float* out = (float*)d_out;

    float *qkv, *Q, *K, *V, *attn, *Bt1, *Bt2;
    cudaGetSymbolAddress((void**)&qkv,  g_qkv);
    cudaGetSymbolAddress((void**)&Q,    g_Q);
    cudaGetSymbolAddress((void**)&K,    g_K);
    cudaGetSymbolAddress((void**)&V,    g_V);
    cudaGetSymbolAddress((void**)&attn, g_attn);
    cudaGetSymbolAddress((void**)&Bt1,  g_Bt1);
    cudaGetSymbolAddress((void**)&Bt2,  g_Bt2);

    cudaFuncSetAttribute(attn_mma_kernel, cudaFuncAttributeMaxDynamicSharedMemorySize,
                         ATT_SMEM);
    cudaFuncSetAttribute(tf32_mma_gemm<true>, cudaFuncAttributeMaxDynamicSharedMemorySize,
                         GEMM_SMEM);
    cudaFuncSetAttribute(tf32_mma_gemm<false>, cudaFuncAttributeMaxDynamicSharedMemorySize,
                         GEMM_SMEM);

    // 0) transpose+round weights
    transpose_round_kernel<<<dim3(3 * HDIM / 32, HDIM / 32), 256>>>(w_qkv, Bt1, HDIM, 3 * HDIM);
    transpose_round_kernel<<<dim3(HDIM / 32, HDIM / 32), 256>>>(w_out, Bt2, HDIM, HDIM);

    // 1) qkv = hidden @ w_qkv + b_qkv (A rounded in-register)
    tf32_mma_gemm<true><<<dim3(3 * HDIM / 128, MROWS / 128), 256, GEMM_SMEM>>>(
        hidden, Bt1, b_qkv, qkv, 3 * HDIM, HDIM);

    // 2) RoPE (Q/K) + V transpose
    rope_kernel<<<MROWS, 256>>>(qkv, Q, K);
    vtrans_kernel<<<dim3(T_SEQ / 32, HD / 32, BATCH * NHEAD), 256>>>(qkv, V);

    // 3) tf32 mma flash attention -> attn [B,T,H] (tf32-rounded)
    attn_mma_kernel<<<dim3(T_SEQ / 128, BATCH * NHEAD), 256, ATT_SMEM>>>(
        Q, K, V, amask, attn);

    // 4) out = attn @ w_out (A already tf32)
    tf32_mma_gemm<false><<<dim3(HDIM / 128, MROWS / 128), 256, GEMM_SMEM>>>(
        attn, Bt2, nullptr, out, HDIM, HDIM);
}

// round 10
// speedup vs baseline: 1.2166x; 1.1520x over previous
#include <cuda_runtime.h>
#include <cuda_fp16.h>
#include <cstdint>
#include <cstddef>

// Problem constants
#define T_SEQ  2048
#define NHEAD  16
#define HDIM   1024
#define HD     64
#define BATCH  2
#define MROWS  (BATCH * T_SEQ)   // 4096

// Scratch (device globals; no allocations allowed)
__device__ float  g_qkv[MROWS * 3 * HDIM];
__device__ float  g_Q[BATCH * NHEAD * T_SEQ * HD];   // [bh][t][d], tf32, pre-scaled
__device__ float  g_K[BATCH * NHEAD * T_SEQ * HD];   // [bh][t][d], tf32
__device__ __half g_Vh[BATCH * NHEAD * T_SEQ * HD];  // [bh][t][d], fp16
__device__ float  g_attn[MROWS * HDIM];              // tf32-rounded attention output
__device__ float  g_Bt1[3 * HDIM * HDIM];            // w_qkv^T rounded [3072,1024]
__device__ float  g_Bt2[HDIM * HDIM];                // w_out^T rounded [1024,1024]

// ---------------------------------------------------------------------------
// Helpers
// ---------------------------------------------------------------------------
__device__ __forceinline__ float to_tf32(float x) {
    uint32_t u;
    asm("cvt.rna.tf32.f32 %0, %1;" : "=r"(u) : "f"(x));
    return __uint_as_float(u);
}

__device__ __forceinline__ uint32_t rnd_u32(uint32_t x) {
    uint32_t u;
    asm("cvt.rna.tf32.f32 %0, %1;" : "=r"(u) : "r"(x));
    return u;
}

// pack two f32 into f16x2: lo in low half, hi in high half
__device__ __forceinline__ uint32_t packh2(float lo, float hi) {
    uint32_t r;
    asm("cvt.rn.f16x2.f32 %0, %1, %2;" : "=r"(r) : "f"(hi), "f"(lo));
    return r;
}

__device__ __forceinline__ void cp16(uint32_t dst, const void* src) {
    asm volatile("cp.async.cg.shared.global [%0], [%1], 16;\n" :: "r"(dst), "l"(src));
}
__device__ __forceinline__ void cp_commit() {
    asm volatile("cp.async.commit_group;\n");
}
__device__ __forceinline__ void cp_wait3() {
    asm volatile("cp.async.wait_group 3;\n");
}
__device__ __forceinline__ void cp_wait1() {
    asm volatile("cp.async.wait_group 1;\n");
}
__device__ __forceinline__ void cp_wait0() {
    asm volatile("cp.async.wait_group 0;\n");
}

__device__ __forceinline__ void mma_tf32(float* c, const uint32_t* a, const uint32_t* b) {
    asm volatile(
        "mma.sync.aligned.m16n8k8.row.col.f32.tf32.tf32.f32 "
        "{%0,%1,%2,%3}, {%4,%5,%6,%7}, {%8,%9}, {%0,%1,%2,%3};"
        : "+f"(c[0]), "+f"(c[1]), "+f"(c[2]), "+f"(c[3])
        : "r"(a[0]), "r"(a[1]), "r"(a[2]), "r"(a[3]), "r"(b[0]), "r"(b[1]));
}

__device__ __forceinline__ void mma_f16(float* c, const uint32_t* a, const uint32_t* b) {
    asm volatile(
        "mma.sync.aligned.m16n8k16.row.col.f32.f16.f16.f32 "
        "{%0,%1,%2,%3}, {%4,%5,%6,%7}, {%8,%9}, {%0,%1,%2,%3};"
        : "+f"(c[0]), "+f"(c[1]), "+f"(c[2]), "+f"(c[3])
        : "r"(a[0]), "r"(a[1]), "r"(a[2]), "r"(a[3]), "r"(b[0]), "r"(b[1]));
}

__device__ __forceinline__ void ldsm4(uint32_t* r, uint32_t addr) {
    asm volatile("ldmatrix.sync.aligned.m8n8.x4.shared.b16 {%0,%1,%2,%3}, [%4];"
        : "=r"(r[0]), "=r"(r[1]), "=r"(r[2]), "=r"(r[3]) : "r"(addr));
}

__device__ __forceinline__ void ldsm4t(uint32_t* r, uint32_t addr) {
    asm volatile("ldmatrix.sync.aligned.m8n8.x4.trans.shared.b16 {%0,%1,%2,%3}, [%4];"
        : "=r"(r[0]), "=r"(r[1]), "=r"(r[2]), "=r"(r[3]) : "r"(addr));
}

// ---------------------------------------------------------------------------
// tf32 mma.sync GEMM — proven mainloop (4-stage, wait3, distance 4),
// ldmatrix fragments, optional in-register tf32 rounding of A (RND).
// ---------------------------------------------------------------------------
#define ASTR 20                          // floats per smem row (16 + 4 pad)
#define STAGE_FLOATS (2 * 128 * ASTR)    // A tile then B tile
#define STAGE_BYTES (STAGE_FLOATS * 4)   // 20480
#define GEMM_SMEM (4 * STAGE_BYTES)      // 81920

template<bool RND>
__global__ __launch_bounds__(256) void tf32_mma_gemm(
    const float* __restrict__ A, const float* __restrict__ Bt,
    const float* __restrict__ bias, float* __restrict__ C,
    int N, int K)
{
    extern __shared__ __align__(128) float smf[];
    const uint32_t sbase = (uint32_t)__cvta_generic_to_shared(smf);

    const int tid = threadIdx.x, lane = tid & 31, w = tid >> 5;
    const int wm = w & 1, wn = w >> 1;           // warp 2x4 grid
    const int g = lane >> 2, tig = lane & 3;
    const int bm = blockIdx.y * 128, bn = blockIdx.x * 128;

    const int lm0 = tid >> 2;            // 0..63
    const int lkq = (tid & 3) * 4;       // 0,4,8,12
    const float* Ag0 = A + (size_t)(bm + lm0) * K + lkq;
    const float* Ag1 = Ag0 + (size_t)64 * K;
    const float* Bg0 = Bt + (size_t)(bn + lm0) * K + lkq;
    const float* Bg1 = Bg0 + (size_t)64 * K;
    const uint32_t offA0 = (lm0 * ASTR + lkq) * 4;
    const uint32_t offA1 = ((lm0 + 64) * ASTR + lkq) * 4;
    const uint32_t offB0 = 128 * ASTR * 4 + offA0;
    const uint32_t offB1 = 128 * ASTR * 4 + offA1;

    const uint32_t a_lrow = (lane & 7) + ((lane >> 3) & 1) * 8;
    const uint32_t a_lk = (lane >> 4) * 4;
    const uint32_t b_lrow = (lane & 7) + ((lane >> 4) & 1) * 8;
    const uint32_t b_lk = ((lane >> 3) & 1) * 4;

    const uint32_t aAddr0 = sbase + ((wm * 64 + a_lrow) * ASTR + a_lk) * 4;
    const uint32_t bAddr0 = sbase + (128 * ASTR + (wn * 32 + b_lrow) * ASTR + b_lk) * 4;

    const int nchunks = K / 16;

#pragma unroll
    for (int s = 0; s < 4; s++) {
        uint32_t so = sbase + s * STAGE_BYTES;
        cp16(so + offA0, Ag0 + s * 16);
        cp16(so + offA1, Ag1 + s * 16);
        cp16(so + offB0, Bg0 + s * 16);
        cp16(so + offB1, Bg1 + s * 16);
        cp_commit();
    }

    float acc[4][4][4] = {};

    for (int c = 0; c < nchunks; c++) {
        cp_wait3();
        __syncthreads();

        const uint32_t st = (c & 3) * STAGE_BYTES;

#pragma unroll
        for (int ks = 0; ks < 16; ks += 8) {
            uint32_t afr[4][4];
#pragma unroll
            for (int i = 0; i < 4; i++) {
                ldsm4(afr[i], aAddr0 + st + (i * 16 * ASTR + ks) * 4);
                if (RND) {
                    afr[i][0] = rnd_u32(afr[i][0]);
                    afr[i][1] = rnd_u32(afr[i][1]);
                    afr[i][2] = rnd_u32(afr[i][2]);
                    afr[i][3] = rnd_u32(afr[i][3]);
                }
            }
            uint32_t bfr[2][4];
#pragma unroll
            for (int jp = 0; jp < 2; jp++)
                ldsm4(bfr[jp], bAddr0 + st + (jp * 16 * ASTR + ks) * 4);
#pragma unroll
            for (int i = 0; i < 4; i++)
#pragma unroll
                for (int jp = 0; jp < 2; jp++) {
                    mma_tf32(acc[i][jp * 2],     afr[i], bfr[jp]);
                    mma_tf32(acc[i][jp * 2 + 1], afr[i], bfr[jp] + 2);
                }
        }
        __syncthreads();

        if (c + 4 < nchunks) {
            uint32_t so = sbase + (c & 3) * STAGE_BYTES;
            const int k0 = (c + 4) * 16;
            cp16(so + offA0, Ag0 + k0);
            cp16(so + offA1, Ag1 + k0);
            cp16(so + offB0, Bg0 + k0);
            cp16(so + offB1, Bg1 + k0);
        }
        cp_commit();
    }

#pragma unroll
    for (int i = 0; i < 4; i++) {
        const int r0 = bm + wm * 64 + i * 16 + g;
#pragma unroll
        for (int j = 0; j < 4; j++) {
            const int c0 = bn + wn * 32 + j * 8 + tig * 2;
            float bx = 0.f, by = 0.f;
            if (bias) { bx = bias[c0]; by = bias[c0 + 1]; }
            float2 o0 = make_float2(acc[i][j][0] + bx, acc[i][j][1] + by);
            float2 o1 = make_float2(acc[i][j][2] + bx, acc[i][j][3] + by);
            *(float2*)&C[(size_t)r0 * N + c0] = o0;
            *(float2*)&C[(size_t)(r0 + 8) * N + c0] = o1;
        }
    }
}

// ---------------------------------------------------------------------------
// Prep: transpose+round (src[K,N] -> dst[N,K])
// ---------------------------------------------------------------------------
__global__ __launch_bounds__(256) void transpose_round_kernel(
    const float* __restrict__ src, float* __restrict__ dst, int K, int N)
{
    __shared__ float t[32][33];
    int n0 = blockIdx.x * 32, k0 = blockIdx.y * 32;
    int x = threadIdx.x & 31, y = threadIdx.x >> 5;   // 32 x 8
#pragma unroll
    for (int i = 0; i < 4; i++)
        t[y + i * 8][x] = src[(size_t)(k0 + y + i * 8) * N + n0 + x];
    __syncthreads();
#pragma unroll
    for (int i = 0; i < 4; i++)
        dst[(size_t)(n0 + y + i * 8) * K + k0 + x] = to_tf32(t[x][y + i * 8]);
}

// ---------------------------------------------------------------------------
// RoPE (Q/K tf32) + V fp16, all coalesced [bh][t][d].
// ---------------------------------------------------------------------------
__global__ __launch_bounds__(256) void rope_kernel(
    const float* __restrict__ qkv,
    float* __restrict__ Q, float* __restrict__ K, __half* __restrict__ Vh)
{
    const int bt = blockIdx.x;
    const int b = bt >> 11;
    const int t = bt & 2047;
    const float* row = qkv + (size_t)bt * (3 * HDIM);
    const float LN1E4_OVER_32 = 0.28782313662425575f;  // ln(10000)/32

#pragma unroll
    for (int it = 0; it < 4; it++) {
        int idx = it * 256 + threadIdx.x;
        int h = idx >> 6;
        int d = idx & 63;
        const float* base = row + h * (3 * HD);
        float qv = base[d];
        float kv = base[HD + d];
        float vv = base[2 * HD + d];
        int fi = d & 31;
        float inv = expf(-(float)fi * LN1E4_OVER_32);
        float ang = (float)t * inv;
        float sv, cv;
        sincosf(ang, &sv, &cv);
        float qrot = (d < 32) ? -base[d + 32] : base[d - 32];
        float krot = (d < 32) ? -base[HD + d + 32] : base[HD + d - 32];
        int bh = b * NHEAD + h;
        size_t o = ((size_t)bh * T_SEQ + t) * HD + d;
        Q[o] = to_tf32((qv * cv + qrot * sv) * 0.125f);
        K[o] = to_tf32(kv * cv + krot * sv);
        Vh[o] = __float2half_rn(vv);
    }
}

// ---------------------------------------------------------------------------
// Flash attention: S = tf32 mma (Q,K), PV = fp16 m16n8k16 mma with P packed
// directly from S accumulators (FA2 register-P; no P smem).
// V consumed fp16 in natural [t][d] layout via ldmatrix.trans.
// ---------------------------------------------------------------------------
#define AQS 68    // float row stride for Qs/Ks
#define VHS 72    // half row stride for Vs (144B rows; ldsm.trans conflict-free)
#define ATT_SMEM ((128 * AQS + 64 * AQS) * 4 + 64 * VHS * 2 + 64 * 4)

__global__ __launch_bounds__(256, 2) void attn_mma_kernel(
    const float* __restrict__ Q, const float* __restrict__ K,
    const __half* __restrict__ Vh, const int* __restrict__ amask,
    float* __restrict__ out)
{
    extern __shared__ __align__(128) float s[];
    float* Qs  = s;                    // [128][AQS]
    float* Ks  = Qs + 128 * AQS;       // [64][AQS]   Ks[key][d]
    __half* Vs = (__half*)(Ks + 64 * AQS);  // [64 keys][VHS] fp16
    int* smask = (int*)(Vs + 64 * VHS);

    const uint32_t sb  = (uint32_t)__cvta_generic_to_shared(s);
    const uint32_t ksb = (uint32_t)__cvta_generic_to_shared(Ks);
    const uint32_t vsb = (uint32_t)__cvta_generic_to_shared(Vs);

    const int tid = threadIdx.x, lane = tid & 31, w = tid >> 5;
    const int g = lane >> 2, tig = lane & 3;
    const int qb = gridDim.x - 1 - blockIdx.x;   // heavy CTAs first
    const int bh = blockIdx.y;
    const int b = bh >> 4, h = bh & 15;

    // Live key-block count (padding is a prefix mask)
    int livev = (amask[b * T_SEQ + lane * 64] != 0) ? 1 : 0;
    unsigned liveb = __ballot_sync(0xffffffff, livev);
    const int nlive = __popc(liveb);

    // ldmatrix per-lane offsets (tf32 S phase)
    const uint32_t a_lrow = (lane & 7) + ((lane >> 3) & 1) * 8;
    const uint32_t a_lk = (lane >> 4) * 4;
    const uint32_t b_lrow = (lane & 7) + ((lane >> 4) & 1) * 8;
    const uint32_t b_lk = ((lane >> 3) & 1) * 4;

    const uint32_t qAddr0 = sb  + ((w * 16 + a_lrow) * AQS + a_lk) * 4;
    const uint32_t kAddr0 = ksb + (b_lrow * AQS + b_lk) * 4;

    // ldmatrix.trans per-lane offsets for V (fp16 B of m16n8k16):
    // lanes 0-15 -> key rows 0-15 at d0; lanes 16-31 -> same rows at d0+8
    const uint32_t v_row = lane & 15;
    const uint32_t v_col = (lane >> 4) * 8;
    const uint32_t vAddr0 = vsb + (v_row * VHS + v_col) * 2;

    // Prologue: Q tile (group 0) + K(0) (group 1)
    const float* Qg = Q + ((size_t)bh * T_SEQ + qb * 128) * HD;
#pragma unroll
    for (int it = 0; it < 8; it++) {
        int idx = it * 256 + tid;
        int r = idx >> 4, c4 = (idx & 15) << 2;
        cp16(sb + (r * AQS + c4) * 4, Qg + r * HD + c4);
    }
    cp_commit();

    const float* Kbase = K + (size_t)bh * T_SEQ * HD;
    const __half* Vbase = Vh + (size_t)bh * T_SEQ * HD;

    {
        const float* Kg = Kbase;   // jb = 0
#pragma unroll
        for (int it = 0; it < 4; it++) {
            int idx = it * 256 + tid;
            int r = idx >> 4, c4 = (idx & 15) << 2;
            cp16(ksb + (r * AQS + c4) * 4, Kg + r * HD + c4);
        }
    }
    cp_commit();

    float accO[8][4] = {};
    float m0 = -1e30f, m1 = -1e30f, l0 = 0.f, l1 = 0.f;

    const int qrow0 = qb * 128 + w * 16 + g;
    const int qrow1 = qrow0 + 8;
    const int nkb = 2 * qb + 2;
    const int jb_end = (nkb < nlive) ? nkb : nlive;

    for (int jb = 0; jb < jb_end; jb++) {
        // 1) K(jb) (and everything older) landed
        cp_wait0();
        __syncthreads();   // K visible; all warps past PV(jb-1) -> Vs free

        // 2) issue V(jb) fp16 loads (2 cp16/thread = 64 rows x 128B) + mask
        {
            const __half* Vg = Vbase + (size_t)jb * 64 * HD;
#pragma unroll
            for (int it = 0; it < 2; it++) {
                int idx = it * 256 + tid;
                int r = idx >> 3, c8 = (idx & 7) << 3;   // 8 halves = 16B
                cp16(vsb + (r * VHS + c8) * 2, Vg + r * HD + c8);
            }
        }
        if (tid < 64) smask[tid] = amask[b * T_SEQ + jb * 64 + tid];
        cp_commit();       // group: V(jb)

        // 3) S = Q_tile @ K_tile^T (tf32)
        float sacc[8][4];
#pragma unroll
        for (int j = 0; j < 8; j++)
            sacc[j][0] = sacc[j][1] = sacc[j][2] = sacc[j][3] = 0.f;
#pragma unroll
        for (int ks = 0; ks < 8; ks++) {
            uint32_t af[4];
            ldsm4(af, qAddr0 + ks * 32);
#pragma unroll
            for (int jp = 0; jp < 4; jp++) {
                uint32_t bf[4];
                ldsm4(bf, kAddr0 + (jp * 16 * AQS + ks * 8) * 4);
                mma_tf32(sacc[jp * 2],     af, bf);
                mma_tf32(sacc[jp * 2 + 1], af, bf + 2);
            }
        }

        __syncthreads();   // all warps done reading Ks; smask visible

        // 4) issue K(jb+1) loads (hidden behind softmax + PV)
        if (jb + 1 < jb_end) {
            const float* Kg = Kbase + (size_t)(jb + 1) * 64 * HD;
#pragma unroll
            for (int it = 0; it < 4; it++) {
                int idx = it * 256 + tid;
                int r = idx >> 4, c4 = (idx & 15) << 2;
                cp16(ksb + (r * AQS + c4) * 4, Kg + r * HD + c4);
            }
        }
        cp_commit();       // group: K(jb+1) (possibly empty)

        // 5) mask + online softmax; P packed to fp16 pairs in registers
        float mx0 = m0, mx1 = m1;
#pragma unroll
        for (int j = 0; j < 8; j++) {
            int c = j * 8 + 2 * tig;
            int colg = jb * 64 + c;
            bool v0 = smask[c]     && (colg     <= qrow0);
            bool v1 = smask[c + 1] && (colg + 1 <= qrow0);
            bool v2 = smask[c]     && (colg     <= qrow1);
            bool v3 = smask[c + 1] && (colg + 1 <= qrow1);
            sacc[j][0] = v0 ? sacc[j][0] : -1e30f;
            sacc[j][1] = v1 ? sacc[j][1] : -1e30f;
            sacc[j][2] = v2 ? sacc[j][2] : -1e30f;
            sacc[j][3] = v3 ? sacc[j][3] : -1e30f;
            mx0 = fmaxf(mx0, fmaxf(sacc[j][0], sacc[j][1]));
            mx1 = fmaxf(mx1, fmaxf(sacc[j][2], sacc[j][3]));
        }
        mx0 = fmaxf(mx0, __shfl_xor_sync(0xffffffff, mx0, 1));
        mx0 = fmaxf(mx0, __shfl_xor_sync(0xffffffff, mx0, 2));
        mx1 = fmaxf(mx1, __shfl_xor_sync(0xffffffff, mx1, 1));
        mx1 = fmaxf(mx1, __shfl_xor_sync(0xffffffff, mx1, 2));
        float corr0 = __expf(m0 - mx0);
        float corr1 = __expf(m1 - mx1);
        m0 = mx0; m1 = mx1;

        uint32_t ph[8][2];   // ph[j][0] = {p(g,2t),p(g,2t+1)}, ph[j][1] = rows g+8
        float sum0 = 0.f, sum1 = 0.f;
#pragma unroll
        for (int j = 0; j < 8; j++) {
            float p0 = __expf(sacc[j][0] - mx0);
            float p1 = __expf(sacc[j][1] - mx0);
            float p2 = __expf(sacc[j][2] - mx1);
            float p3 = __expf(sacc[j][3] - mx1);
            ph[j][0] = packh2(p0, p1);
            ph[j][1] = packh2(p2, p3);
            // sum the fp16-ROUNDED values so l matches the PV matmul
            float2 f0 = __half22float2(*(__half2*)&ph[j][0]);
            float2 f1 = __half22float2(*(__half2*)&ph[j][1]);
            sum0 += f0.x + f0.y;
            sum1 += f1.x + f1.y;
        }
        sum0 += __shfl_xor_sync(0xffffffff, sum0, 1);
        sum0 += __shfl_xor_sync(0xffffffff, sum0, 2);
        sum1 += __shfl_xor_sync(0xffffffff, sum1, 1);
        sum1 += __shfl_xor_sync(0xffffffff, sum1, 2);
        l0 = l0 * corr0 + sum0;
        l1 = l1 * corr1 + sum1;

#pragma unroll
        for (int j = 0; j < 8; j++) {
            accO[j][0] *= corr0; accO[j][1] *= corr0;
            accO[j][2] *= corr1; accO[j][3] *= corr1;
        }

        // 6) wait V(jb) (K(jb+1) may stay in flight), then PV (fp16 m16n8k16)
        cp_wait1();
        __syncthreads();   // V visible to all warps

#pragma unroll
        for (int kk = 0; kk < 4; kk++) {   // k16 blocks over 64 keys
            uint32_t pa[4] = { ph[2 * kk][0], ph[2 * kk][1],
                               ph[2 * kk + 1][0], ph[2 * kk + 1][1] };
#pragma unroll
            for (int jp = 0; jp < 4; jp++) {   // d16 blocks over 64 dims
                uint32_t bf[4];
                ldsm4t(bf, vAddr0 + (kk * 16 * VHS + jp * 16) * 2);
                mma_f16(accO[jp * 2],     pa, bf);
                mma_f16(accO[jp * 2 + 1], pa, bf + 2);
            }
        }
    }

    // ---- epilogue (tf32-rounded; out-GEMM runs RND=false) ----
    float inv0 = 1.f / l0, inv1 = 1.f / l1;
    const int r0 = b * T_SEQ + qb * 128 + w * 16 + g;
#pragma unroll
    for (int j = 0; j < 8; j++) {
        int c = h * HD + j * 8 + 2 * tig;
        float2 o0 = make_float2(to_tf32(accO[j][0] * inv0), to_tf32(accO[j][1] * inv0));
        float2 o1 = make_float2(to_tf32(accO[j][2] * inv1), to_tf32(accO[j][3] * inv1));
        *(float2*)&out[(size_t)r0 * HDIM + c] = o0;
        *(float2*)&out[(size_t)(r0 + 8) * HDIM + c] = o1;
    }
}

// ---------------------------------------------------------------------------
// Launch
// ---------------------------------------------------------------------------
extern "C" void kernel_launch(void* const* d_in, const int* in_sizes, int n_in,
                              void* d_out, int out_size)
{
    const float* hidden = (const float*)d_in[0];
    const int*   amask  = (const int*)d_in[1];
    const float* w_qkv  = (const float*)d_in[2];
    const float* b_qkv  = (const float*)d_in[3];
    const float* w_out  = (const float*)d_in[4];
    float* out = (float*)d_out;

    float *qkv, *Q, *K, *attn, *Bt1, *Bt2;
    __half* Vh;
    cudaGetSymbolAddress((void**)&qkv,  g_qkv);
    cudaGetSymbolAddress((void**)&Q,    g_Q);
    cudaGetSymbolAddress((void**)&K,    g_K);
    cudaGetSymbolAddress((void**)&Vh,   g_Vh);
    cudaGetSymbolAddress((void**)&attn, g_attn);
    cudaGetSymbolAddress((void**)&Bt1,  g_Bt1);
    cudaGetSymbolAddress((void**)&Bt2,  g_Bt2);

    cudaFuncSetAttribute(attn_mma_kernel, cudaFuncAttributeMaxDynamicSharedMemorySize,
                         ATT_SMEM);
    cudaFuncSetAttribute(tf32_mma_gemm<true>, cudaFuncAttributeMaxDynamicSharedMemorySize,
                         GEMM_SMEM);
    cudaFuncSetAttribute(tf32_mma_gemm<false>, cudaFuncAttributeMaxDynamicSharedMemorySize,
                         GEMM_SMEM);

    // 0) transpose+round weights
    transpose_round_kernel<<<dim3(3 * HDIM / 32, HDIM / 32), 256>>>(w_qkv, Bt1, HDIM, 3 * HDIM);
    transpose_round_kernel<<<dim3(HDIM / 32, HDIM / 32), 256>>>(w_out, Bt2, HDIM, HDIM);

    // 1) qkv = hidden @ w_qkv + b_qkv (A rounded in-register)
    tf32_mma_gemm<true><<<dim3(3 * HDIM / 128, MROWS / 128), 256, GEMM_SMEM>>>(
        hidden, Bt1, b_qkv, qkv, 3 * HDIM, HDIM);

    // 2) RoPE (Q/K tf32) + V fp16, all coalesced
    rope_kernel<<<MROWS, 256>>>(qkv, Q, K, Vh);

    // 3) flash attention (tf32 S, fp16 register-P PV) -> attn
    attn_mma_kernel<<<dim3(T_SEQ / 128, BATCH * NHEAD), 256, ATT_SMEM>>>(
        Q, K, Vh, amask, attn);

    // 4) out = attn @ w_out (A already tf32)
    tf32_mma_gemm<false><<<dim3(HDIM / 128, MROWS / 128), 256, GEMM_SMEM>>>(
        attn, Bt2, nullptr, out, HDIM, HDIM);
}

// round 11
// speedup vs baseline: 1.9073x; 1.5678x over previous
#include <cuda_runtime.h>
#include <cuda_fp16.h>
#include <cstdint>
#include <cstddef>

// Problem constants
#define T_SEQ  2048
#define NHEAD  16
#define HDIM   1024
#define HD     64
#define BATCH  2
#define MROWS  (BATCH * T_SEQ)   // 4096

// Scratch (device globals; no allocations allowed)
__device__ float  g_qkv[MROWS * 3 * HDIM];            // fp32 (rope input precision)
__device__ __half g_hh[MROWS * HDIM];                 // hidden fp16
__device__ __half g_Qh[BATCH * NHEAD * T_SEQ * HD];   // [bh][t][d], fp16, pre-scaled
__device__ __half g_Kh[BATCH * NHEAD * T_SEQ * HD];   // [bh][t][d], fp16
__device__ __half g_Vh[BATCH * NHEAD * T_SEQ * HD];   // [bh][t][d], fp16
__device__ __half g_attn[MROWS * HDIM];               // attention output fp16
__device__ __half g_Bt1[3 * HDIM * HDIM];             // w_qkv^T fp16 [3072,1024]
__device__ __half g_Bt2[HDIM * HDIM];                 // w_out^T fp16 [1024,1024]

// ---------------------------------------------------------------------------
// Helpers
// ---------------------------------------------------------------------------
__device__ __forceinline__ uint32_t packh2(float lo, float hi) {
    uint32_t r;
    asm("cvt.rn.f16x2.f32 %0, %1, %2;" : "=r"(r) : "f"(hi), "f"(lo));
    return r;
}

__device__ __forceinline__ void cp16(uint32_t dst, const void* src) {
    asm volatile("cp.async.cg.shared.global [%0], [%1], 16;\n" :: "r"(dst), "l"(src));
}
__device__ __forceinline__ void cp_commit() {
    asm volatile("cp.async.commit_group;\n");
}
__device__ __forceinline__ void cp_wait3() {
    asm volatile("cp.async.wait_group 3;\n");
}
__device__ __forceinline__ void cp_wait1() {
    asm volatile("cp.async.wait_group 1;\n");
}
__device__ __forceinline__ void cp_wait0() {
    asm volatile("cp.async.wait_group 0;\n");
}

__device__ __forceinline__ void mma_f16(float* c, const uint32_t* a, const uint32_t* b) {
    asm volatile(
        "mma.sync.aligned.m16n8k16.row.col.f32.f16.f16.f32 "
        "{%0,%1,%2,%3}, {%4,%5,%6,%7}, {%8,%9}, {%0,%1,%2,%3};"
        : "+f"(c[0]), "+f"(c[1]), "+f"(c[2]), "+f"(c[3])
        : "r"(a[0]), "r"(a[1]), "r"(a[2]), "r"(a[3]), "r"(b[0]), "r"(b[1]));
}

__device__ __forceinline__ void ldsm4(uint32_t* r, uint32_t addr) {
    asm volatile("ldmatrix.sync.aligned.m8n8.x4.shared.b16 {%0,%1,%2,%3}, [%4];"
        : "=r"(r[0]), "=r"(r[1]), "=r"(r[2]), "=r"(r[3]) : "r"(addr));
}

__device__ __forceinline__ void ldsm4t(uint32_t* r, uint32_t addr) {
    asm volatile("ldmatrix.sync.aligned.m8n8.x4.trans.shared.b16 {%0,%1,%2,%3}, [%4];"
        : "=r"(r[0]), "=r"(r[1]), "=r"(r[2]), "=r"(r[3]) : "r"(addr));
}

// ---------------------------------------------------------------------------
// fp16 mma.sync GEMM — proven pipeline shape (4-stage, wait3, distance 4).
// C[M,N] = Ah[M,K] @ Bth[N,K]^T (+bias), fp32 accumulate/output.
// 128x128x32 CTA chunk, 256 threads, 8 warps (2x4), warp tile 64x32.
// ---------------------------------------------------------------------------
#define HSTR 40                            // halves per smem row (32 + 8 pad), 80B
#define HSTAGE_BYTES (2 * 128 * HSTR * 2)  // A tile then B tile = 20480
#define HGEMM_SMEM (4 * HSTAGE_BYTES)      // 81920

__global__ __launch_bounds__(256) void h16_mma_gemm(
    const __half* __restrict__ A, const __half* __restrict__ Bt,
    const float* __restrict__ bias, float* __restrict__ C,
    int N, int K)
{
    extern __shared__ __align__(128) char smc[];
    const uint32_t sbase = (uint32_t)__cvta_generic_to_shared(smc);

    const int tid = threadIdx.x, lane = tid & 31, w = tid >> 5;
    const int wm = w & 1, wn = w >> 1;           // warp 2x4 grid
    const int g = lane >> 2, tig = lane & 3;
    const int bm = blockIdx.y * 128, bn = blockIdx.x * 128;

    // cp.async mapping: per tile 512 cp16 (rows 0-63 + 64-127), 2 each/thread
    const int r0w = tid >> 2;            // 0..63
    const int c8 = (tid & 3) * 8;        // halves: 0,8,16,24
    const __half* Ag0 = A + (size_t)(bm + r0w) * K + c8;
    const __half* Ag1 = Ag0 + (size_t)64 * K;
    const __half* Bg0 = Bt + (size_t)(bn + r0w) * K + c8;
    const __half* Bg1 = Bg0 + (size_t)64 * K;
    const uint32_t offA0 = (r0w * HSTR + c8) * 2;
    const uint32_t offA1 = ((r0w + 64) * HSTR + c8) * 2;
    const uint32_t offB0 = 128 * HSTR * 2 + offA0;
    const uint32_t offB1 = 128 * HSTR * 2 + offA1;

    // ldmatrix per-lane offsets (halves)
    const uint32_t a_row = (lane & 7) + ((lane >> 3) & 1) * 8;
    const uint32_t a_c8 = (lane >> 4) * 8;
    const uint32_t b_row = (lane & 7) + ((lane >> 4) & 1) * 8;
    const uint32_t b_c8 = ((lane >> 3) & 1) * 8;

    const uint32_t aAddr0 = sbase + ((wm * 64 + a_row) * HSTR + a_c8) * 2;
    const uint32_t bAddr0 = sbase + (128 * HSTR + (wn * 32 + b_row) * HSTR + b_c8) * 2;

    const int nchunks = K / 32;

    // Prologue: 4 stages (prefetch distance 4)
#pragma unroll
    for (int s = 0; s < 4; s++) {
        uint32_t so = sbase + s * HSTAGE_BYTES;
        cp16(so + offA0, Ag0 + s * 32);
        cp16(so + offA1, Ag1 + s * 32);
        cp16(so + offB0, Bg0 + s * 32);
        cp16(so + offB1, Bg1 + s * 32);
        cp_commit();
    }

    float acc[4][4][4] = {};

    for (int c = 0; c < nchunks; c++) {
        cp_wait3();
        __syncthreads();

        const uint32_t st = (c & 3) * HSTAGE_BYTES;

#pragma unroll
        for (int ks = 0; ks < 32; ks += 16) {
            uint32_t afr[4][4];
#pragma unroll
            for (int i = 0; i < 4; i++)
                ldsm4(afr[i], aAddr0 + st + (i * 16 * HSTR + ks) * 2);
            uint32_t bfr[2][4];
#pragma unroll
            for (int jp = 0; jp < 2; jp++)
                ldsm4(bfr[jp], bAddr0 + st + (jp * 16 * HSTR + ks) * 2);
#pragma unroll
            for (int i = 0; i < 4; i++)
#pragma unroll
                for (int jp = 0; jp < 2; jp++) {
                    mma_f16(acc[i][jp * 2],     afr[i], bfr[jp]);
                    mma_f16(acc[i][jp * 2 + 1], afr[i], bfr[jp] + 2);
                }
        }
        __syncthreads();

        if (c + 4 < nchunks) {
            uint32_t so = sbase + (c & 3) * HSTAGE_BYTES;
            const int k0 = (c + 4) * 32;
            cp16(so + offA0, Ag0 + k0);
            cp16(so + offA1, Ag1 + k0);
            cp16(so + offB0, Bg0 + k0);
            cp16(so + offB1, Bg1 + k0);
        }
        cp_commit();
    }

#pragma unroll
    for (int i = 0; i < 4; i++) {
        const int r0 = bm + wm * 64 + i * 16 + g;
#pragma unroll
        for (int j = 0; j < 4; j++) {
            const int c0 = bn + wn * 32 + j * 8 + tig * 2;
            float bx = 0.f, by = 0.f;
            if (bias) { bx = bias[c0]; by = bias[c0 + 1]; }
            float2 o0 = make_float2(acc[i][j][0] + bx, acc[i][j][1] + by);
            float2 o1 = make_float2(acc[i][j][2] + bx, acc[i][j][3] + by);
            *(float2*)&C[(size_t)r0 * N + c0] = o0;
            *(float2*)&C[(size_t)(r0 + 8) * N + c0] = o1;
        }
    }
}

// ---------------------------------------------------------------------------
// Prep: fp32->fp16 copy; transpose to fp16 (src[K,N] -> dst[N,K])
// ---------------------------------------------------------------------------
__global__ __launch_bounds__(256) void f2h_kernel(
    const float* __restrict__ src, __half* __restrict__ dst)
{
    int i = blockIdx.x * 256 + threadIdx.x;
    float4 v = ((const float4*)src)[i];
    __half2 h0 = __floats2half2_rn(v.x, v.y);
    __half2 h1 = __floats2half2_rn(v.z, v.w);
    ((__half2*)dst)[2 * i]     = h0;
    ((__half2*)dst)[2 * i + 1] = h1;
}

__global__ __launch_bounds__(256) void transpose_h_kernel(
    const float* __restrict__ src, __half* __restrict__ dst, int K, int N)
{
    __shared__ float t[32][33];
    int n0 = blockIdx.x * 32, k0 = blockIdx.y * 32;
    int x = threadIdx.x & 31, y = threadIdx.x >> 5;   // 32 x 8
#pragma unroll
    for (int i = 0; i < 4; i++)
        t[y + i * 8][x] = src[(size_t)(k0 + y + i * 8) * N + n0 + x];
    __syncthreads();
#pragma unroll
    for (int i = 0; i < 4; i++)
        dst[(size_t)(n0 + y + i * 8) * K + k0 + x] = __float2half_rn(t[x][y + i * 8]);
}

// ---------------------------------------------------------------------------
// RoPE: qkv fp32 -> Q/K/V fp16, coalesced [bh][t][d]. Q pre-scaled 1/8.
// ---------------------------------------------------------------------------
__global__ __launch_bounds__(256) void rope_kernel(
    const float* __restrict__ qkv,
    __half* __restrict__ Q, __half* __restrict__ K, __half* __restrict__ Vh)
{
    const int bt = blockIdx.x;
    const int b = bt >> 11;
    const int t = bt & 2047;
    const float* row = qkv + (size_t)bt * (3 * HDIM);
    const float LN1E4_OVER_32 = 0.28782313662425575f;  // ln(10000)/32

#pragma unroll
    for (int it = 0; it < 4; it++) {
        int idx = it * 256 + threadIdx.x;
        int h = idx >> 6;
        int d = idx & 63;
        const float* base = row + h * (3 * HD);
        float qv = base[d];
        float kv = base[HD + d];
        float vv = base[2 * HD + d];
        int fi = d & 31;
        float inv = expf(-(float)fi * LN1E4_OVER_32);
        float ang = (float)t * inv;
        float sv, cv;
        sincosf(ang, &sv, &cv);
        float qrot = (d < 32) ? -base[d + 32] : base[d - 32];
        float krot = (d < 32) ? -base[HD + d + 32] : base[HD + d - 32];
        int bh = b * NHEAD + h;
        size_t o = ((size_t)bh * T_SEQ + t) * HD + d;
        Q[o] = __float2half_rn((qv * cv + qrot * sv) * 0.125f);
        K[o] = __float2half_rn(kv * cv + krot * sv);
        Vh[o] = __float2half_rn(vv);
    }
}

// ---------------------------------------------------------------------------
// Flash attention, all-fp16 MMA inputs (fp32 accum):
// S = fp16 m16n8k16 (Q ldsm, K ldsm), PV = fp16 register-P + V ldsm.trans.
// ---------------------------------------------------------------------------
#define QHS 72    // half row stride (144B), conflict-free for ldsm/ldsm.trans
#define ATT_SMEM ((128 + 64 + 64) * QHS * 2 + 64 * 4)

__global__ __launch_bounds__(256, 2) void attn_mma_kernel(
    const __half* __restrict__ Q, const __half* __restrict__ K,
    const __half* __restrict__ Vh, const int* __restrict__ amask,
    __half* __restrict__ out)
{
    extern __shared__ __align__(128) char smc[];
    __half* Qs = (__half*)smc;               // [128][QHS]
    __half* Ks = Qs + 128 * QHS;             // [64][QHS]  Ks[key][d]
    __half* Vs = Ks + 64 * QHS;              // [64][QHS]  Vs[key][d]
    int* smask = (int*)(Vs + 64 * QHS);

    const uint32_t qsb = (uint32_t)__cvta_generic_to_shared(Qs);
    const uint32_t ksb = (uint32_t)__cvta_generic_to_shared(Ks);
    const uint32_t vsb = (uint32_t)__cvta_generic_to_shared(Vs);

    const int tid = threadIdx.x, lane = tid & 31, w = tid >> 5;
    const int g = lane >> 2, tig = lane & 3;
    const int qb = gridDim.x - 1 - blockIdx.x;   // heavy CTAs first
    const int bh = blockIdx.y;
    const int b = bh >> 4, h = bh & 15;

    // Live key-block count (padding is a prefix mask)
    int livev = (amask[b * T_SEQ + lane * 64] != 0) ? 1 : 0;
    unsigned liveb = __ballot_sync(0xffffffff, livev);
    const int nlive = __popc(liveb);

    // ldmatrix per-lane offsets (halves)
    const uint32_t a_row = (lane & 7) + ((lane >> 3) & 1) * 8;
    const uint32_t a_c8 = (lane >> 4) * 8;
    const uint32_t b_row = (lane & 7) + ((lane >> 4) & 1) * 8;
    const uint32_t b_c8 = ((lane >> 3) & 1) * 8;

    const uint32_t qAddr0 = qsb + ((w * 16 + a_row) * QHS + a_c8) * 2;
    const uint32_t kAddr0 = ksb + (b_row * QHS + b_c8) * 2;

    // ldsm.trans per-lane offsets for V fragments (B of m16n8k16)
    const uint32_t v_row = lane & 15;
    const uint32_t v_c8 = (lane >> 4) * 8;
    const uint32_t vAddr0 = vsb + (v_row * QHS + v_c8) * 2;

    // Prologue: Q tile (group 0) + K(0) (group 1)
    const __half* Qg = Q + ((size_t)bh * T_SEQ + qb * 128) * HD;
#pragma unroll
    for (int it = 0; it < 4; it++) {
        int idx = it * 256 + tid;
        int r = idx >> 3, c8 = (idx & 7) << 3;
        cp16(qsb + (r * QHS + c8) * 2, Qg + r * HD + c8);
    }
    cp_commit();

    const __half* Kbase = K + (size_t)bh * T_SEQ * HD;
    const __half* Vbase = Vh + (size_t)bh * T_SEQ * HD;

    {
        const __half* Kg = Kbase;   // jb = 0
#pragma unroll
        for (int it = 0; it < 2; it++) {
            int idx = it * 256 + tid;
            int r = idx >> 3, c8 = (idx & 7) << 3;
            cp16(ksb + (r * QHS + c8) * 2, Kg + r * HD + c8);
        }
    }
    cp_commit();

    float accO[8][4] = {};
    float m0 = -1e30f, m1 = -1e30f, l0 = 0.f, l1 = 0.f;

    const int qrow0 = qb * 128 + w * 16 + g;
    const int qrow1 = qrow0 + 8;
    const int nkb = 2 * qb + 2;
    const int jb_end = (nkb < nlive) ? nkb : nlive;

    for (int jb = 0; jb < jb_end; jb++) {
        // 1) K(jb) (and everything older) landed
        cp_wait0();
        __syncthreads();   // K visible; all warps past PV(jb-1) -> Vs free

        // 2) issue V(jb) loads + mask
        {
            const __half* Vg = Vbase + (size_t)jb * 64 * HD;
#pragma unroll
            for (int it = 0; it < 2; it++) {
                int idx = it * 256 + tid;
                int r = idx >> 3, c8 = (idx & 7) << 3;
                cp16(vsb + (r * QHS + c8) * 2, Vg + r * HD + c8);
            }
        }
        if (tid < 64) smask[tid] = amask[b * T_SEQ + jb * 64 + tid];
        cp_commit();       // group: V(jb)

        // 3) S = Q_tile @ K_tile^T (fp16 m16n8k16)
        float sacc[8][4];
#pragma unroll
        for (int j = 0; j < 8; j++)
            sacc[j][0] = sacc[j][1] = sacc[j][2] = sacc[j][3] = 0.f;
#pragma unroll
        for (int ks = 0; ks < 64; ks += 16) {
            uint32_t af[4];
            ldsm4(af, qAddr0 + ks * 2);
#pragma unroll
            for (int jp = 0; jp < 4; jp++) {
                uint32_t bf[4];
                ldsm4(bf, kAddr0 + (jp * 16 * QHS + ks) * 2);
                mma_f16(sacc[jp * 2],     af, bf);
                mma_f16(sacc[jp * 2 + 1], af, bf + 2);
            }
        }

        __syncthreads();   // all warps done reading Ks; smask visible

        // 4) issue K(jb+1) loads (hidden behind softmax + PV)
        if (jb + 1 < jb_end) {
            const __half* Kg = Kbase + (size_t)(jb + 1) * 64 * HD;
#pragma unroll
            for (int it = 0; it < 2; it++) {
                int idx = it * 256 + tid;
                int r = idx >> 3, c8 = (idx & 7) << 3;
                cp16(ksb + (r * QHS + c8) * 2, Kg + r * HD + c8);
            }
        }
        cp_commit();       // group: K(jb+1) (possibly empty)

        // 5) mask + online softmax; P packed to fp16 pairs in registers
        float mx0 = m0, mx1 = m1;
#pragma unroll
        for (int j = 0; j < 8; j++) {
            int c = j * 8 + 2 * tig;
            int colg = jb * 64 + c;
            bool v0 = smask[c]     && (colg     <= qrow0);
            bool v1 = smask[c + 1] && (colg + 1 <= qrow0);
            bool v2 = smask[c]     && (colg     <= qrow1);
            bool v3 = smask[c + 1] && (colg + 1 <= qrow1);
            sacc[j][0] = v0 ? sacc[j][0] : -1e30f;
            sacc[j][1] = v1 ? sacc[j][1] : -1e30f;
            sacc[j][2] = v2 ? sacc[j][2] : -1e30f;
            sacc[j][3] = v3 ? sacc[j][3] : -1e30f;
            mx0 = fmaxf(mx0, fmaxf(sacc[j][0], sacc[j][1]));
            mx1 = fmaxf(mx1, fmaxf(sacc[j][2], sacc[j][3]));
        }
        mx0 = fmaxf(mx0, __shfl_xor_sync(0xffffffff, mx0, 1));
        mx0 = fmaxf(mx0, __shfl_xor_sync(0xffffffff, mx0, 2));
        mx1 = fmaxf(mx1, __shfl_xor_sync(0xffffffff, mx1, 1));
        mx1 = fmaxf(mx1, __shfl_xor_sync(0xffffffff, mx1, 2));
        float corr0 = __expf(m0 - mx0);
        float corr1 = __expf(m1 - mx1);
        m0 = mx0; m1 = mx1;

        uint32_t ph[8][2];
        float sum0 = 0.f, sum1 = 0.f;
#pragma unroll
        for (int j = 0; j < 8; j++) {
            float p0 = __expf(sacc[j][0] - mx0);
            float p1 = __expf(sacc[j][1] - mx0);
            float p2 = __expf(sacc[j][2] - mx1);
            float p3 = __expf(sacc[j][3] - mx1);
            ph[j][0] = packh2(p0, p1);
            ph[j][1] = packh2(p2, p3);
            float2 f0 = __half22float2(*(__half2*)&ph[j][0]);
            float2 f1 = __half22float2(*(__half2*)&ph[j][1]);
            sum0 += f0.x + f0.y;
            sum1 += f1.x + f1.y;
        }
        sum0 += __shfl_xor_sync(0xffffffff, sum0, 1);
        sum0 += __shfl_xor_sync(0xffffffff, sum0, 2);
        sum1 += __shfl_xor_sync(0xffffffff, sum1, 1);
        sum1 += __shfl_xor_sync(0xffffffff, sum1, 2);
        l0 = l0 * corr0 + sum0;
        l1 = l1 * corr1 + sum1;

#pragma unroll
        for (int j = 0; j < 8; j++) {
            accO[j][0] *= corr0; accO[j][1] *= corr0;
            accO[j][2] *= corr1; accO[j][3] *= corr1;
        }

        // 6) wait V(jb) (K(jb+1) may stay in flight), then PV
        cp_wait1();
        __syncthreads();   // V visible to all warps

#pragma unroll
        for (int kk = 0; kk < 4; kk++) {   // k16 blocks over 64 keys
            uint32_t pa[4] = { ph[2 * kk][0], ph[2 * kk][1],
                               ph[2 * kk + 1][0], ph[2 * kk + 1][1] };
#pragma unroll
            for (int jp = 0; jp < 4; jp++) {   // d16 blocks over 64 dims
                uint32_t bf[4];
                ldsm4t(bf, vAddr0 + (kk * 16 * QHS + jp * 16) * 2);
                mma_f16(accO[jp * 2],     pa, bf);
                mma_f16(accO[jp * 2 + 1], pa, bf + 2);
            }
        }
    }

    // ---- epilogue: fp16 output (A operand of the out-GEMM) ----
    float inv0 = 1.f / l0, inv1 = 1.f / l1;
    const int r0 = b * T_SEQ + qb * 128 + w * 16 + g;
#pragma unroll
    for (int j = 0; j < 8; j++) {
        int c = h * HD + j * 8 + 2 * tig;
        uint32_t o0 = packh2(accO[j][0] * inv0, accO[j][1] * inv0);
        uint32_t o1 = packh2(accO[j][2] * inv1, accO[j][3] * inv1);
        *(uint32_t*)&out[(size_t)r0 * HDIM + c] = o0;
        *(uint32_t*)&out[(size_t)(r0 + 8) * HDIM + c] = o1;
    }
}

// ---------------------------------------------------------------------------
// Launch
// ---------------------------------------------------------------------------
extern "C" void kernel_launch(void* const* d_in, const int* in_sizes, int n_in,
                              void* d_out, int out_size)
{
    const float* hidden = (const float*)d_in[0];
    const int*   amask  = (const int*)d_in[1];
    const float* w_qkv  = (const float*)d_in[2];
    const float* b_qkv  = (const float*)d_in[3];
    const float* w_out  = (const float*)d_in[4];
    float* out = (float*)d_out;

    float* qkv;
    __half *hh, *Qh, *Kh, *Vh, *attn, *Bt1, *Bt2;
    cudaGetSymbolAddress((void**)&qkv,  g_qkv);
    cudaGetSymbolAddress((void**)&hh,   g_hh);
    cudaGetSymbolAddress((void**)&Qh,   g_Qh);
    cudaGetSymbolAddress((void**)&Kh,   g_Kh);
    cudaGetSymbolAddress((void**)&Vh,   g_Vh);
    cudaGetSymbolAddress((void**)&attn, g_attn);
    cudaGetSymbolAddress((void**)&Bt1,  g_Bt1);
    cudaGetSymbolAddress((void**)&Bt2,  g_Bt2);

    cudaFuncSetAttribute(h16_mma_gemm, cudaFuncAttributeMaxDynamicSharedMemorySize,
                         HGEMM_SMEM);
    cudaFuncSetAttribute(attn_mma_kernel, cudaFuncAttributeMaxDynamicSharedMemorySize,
                         ATT_SMEM);

    // 0) prep: hidden->fp16; weights transpose->fp16
    f2h_kernel<<<MROWS * HDIM / 4 / 256, 256>>>(hidden, hh);
    transpose_h_kernel<<<dim3(3 * HDIM / 32, HDIM / 32), 256>>>(w_qkv, Bt1, HDIM, 3 * HDIM);
    transpose_h_kernel<<<dim3(HDIM / 32, HDIM / 32), 256>>>(w_out, Bt2, HDIM, HDIM);

    // 1) qkv = hidden @ w_qkv + b_qkv (fp16 MMA, fp32 accum/out)
    h16_mma_gemm<<<dim3(3 * HDIM / 128, MROWS / 128), 256, HGEMM_SMEM>>>(
        hh, Bt1, b_qkv, qkv, 3 * HDIM, HDIM);

    // 2) RoPE -> fp16 Q/K/V
    rope_kernel<<<MROWS, 256>>>(qkv, Qh, Kh, Vh);

    // 3) flash attention (all fp16 MMA) -> attn fp16
    attn_mma_kernel<<<dim3(T_SEQ / 128, BATCH * NHEAD), 256, ATT_SMEM>>>(
        Qh, Kh, Vh, amask, attn);

    // 4) out = attn @ w_out (fp16 MMA, fp32 out)
    h16_mma_gemm<<<dim3(HDIM / 128, MROWS / 128), 256, HGEMM_SMEM>>>(
        attn, Bt2, nullptr, out, HDIM, HDIM);
}